// round 1
// baseline (speedup 1.0000x reference)
#include <cuda_runtime.h>
#include <cuda_bf16.h>
#include <cstdint>

// Problem constants
#define Nn   400000
#define Hh   256
#define Cc   128
#define Aa   32
#define Gg   512
#define NGg  1024
#define CpA  (Cc + Aa)          // 160
#define BN_EPS 1e-5f

#define TILE_M 64
#define KB     16
#define CM     (3 * Cc)         // 384 virtual channels: [g1 | g2 | t]

// ---------------- scratch (no allocations allowed) ----------------
__device__ float g_readout[NGg * Cc];   // segment sums  [1024,128]
__device__ float g_scale[CpA];          // gamma / sqrt(var+eps)
__device__ float g_shift[CpA];          // beta - mean*scale
__device__ float g_hidden[NGg * Gg];    // MLP hidden    [1024,512]

// ---------------- packed f32x2 helpers (Blackwell FFMA2) ----------------
__device__ __forceinline__ unsigned long long pack2(float lo, float hi) {
    unsigned long long r;
    asm("mov.b64 %0, {%1, %2};" : "=l"(r) : "f"(lo), "f"(hi));
    return r;
}
__device__ __forceinline__ void unpack2(unsigned long long v, float& lo, float& hi) {
    asm("mov.b64 {%0, %1}, %2;" : "=f"(lo), "=f"(hi) : "l"(v));
}
__device__ __forceinline__ unsigned long long fma2(unsigned long long a,
                                                   unsigned long long b,
                                                   unsigned long long c) {
    unsigned long long d;
    asm("fma.rn.f32x2 %0, %1, %2, %3;" : "=l"(d) : "l"(a), "l"(b), "l"(c));
    return d;
}

// ---------------- kernel 0: zero the segment-sum buffer ----------------
__global__ void zero_kernel() {
    int i = blockIdx.x * blockDim.x + threadIdx.x;
    if (i < NGg * Cc) g_readout[i] = 0.0f;
}

// ---------------- kernel 1: fused node GEMMs + gate + segment-sum ----------------
// Per block: 64 nodes x 384 channels (g1 from init@WgTop, g2 from final@WgBot,
// t from final@Wt). Thread (tm,tc) = (tid>>4, tid&15): 4 nodes x 8 channels x 3 mats.
__global__ __launch_bounds__(256, 1)
void node_kernel(const float* __restrict__ xinit, const float* __restrict__ xfin,
                 const int* __restrict__ gids,
                 const float* __restrict__ Wg, const float* __restrict__ bg,
                 const float* __restrict__ Wt, const float* __restrict__ bt) {
    __shared__ float s_in[2][TILE_M][KB + 1];                   // [init/final][node][k]
    __shared__ union { float w[KB][CM]; float out[TILE_M][Cc]; } s;
    __shared__ int s_gid[TILE_M];

    const int tid = threadIdx.x;
    const int tm = tid >> 4;        // 0..15 -> 4 nodes each
    const int tc = tid & 15;        // 0..15 -> 8 channels each
    const int c0 = tc * 8;
    const int nodeBase = blockIdx.x * TILE_M;

    if (tid < TILE_M) s_gid[tid] = gids[nodeBase + tid];

    unsigned long long acc[4][3][4];        // [node][matrix][chan-pair]
#pragma unroll
    for (int i = 0; i < 4; i++)
#pragma unroll
        for (int m = 0; m < 3; m++)
#pragma unroll
            for (int j = 0; j < 4; j++) acc[i][m][j] = 0ULL;

    for (int chunk = 0; chunk < Hh / KB; ++chunk) {
        const int k0 = chunk * KB;
        __syncthreads();
        // load 64x16 of init and final (1 float4 per thread per input)
        {
            int n = tid >> 2, q = tid & 3;
            float4 v = *(const float4*)(xinit + (size_t)(nodeBase + n) * Hh + k0 + 4 * q);
            s_in[0][n][4 * q + 0] = v.x; s_in[0][n][4 * q + 1] = v.y;
            s_in[0][n][4 * q + 2] = v.z; s_in[0][n][4 * q + 3] = v.w;
            float4 u = *(const float4*)(xfin + (size_t)(nodeBase + n) * Hh + k0 + 4 * q);
            s_in[1][n][4 * q + 0] = u.x; s_in[1][n][4 * q + 1] = u.y;
            s_in[1][n][4 * q + 2] = u.z; s_in[1][n][4 * q + 3] = u.w;
        }
        // load 16x384 weights: [WgTop | WgBot | Wt]
#pragma unroll
        for (int it = 0; it < (KB * CM / 4) / 256; ++it) {
            int f = tid + it * 256;
            int k = f / 96;
            int c4 = (f % 96) * 4;
            float4 wv;
            if (c4 < Cc)            wv = *(const float4*)(Wg + (size_t)(k0 + k) * Cc + c4);
            else if (c4 < 2 * Cc)   wv = *(const float4*)(Wg + (size_t)(Hh + k0 + k) * Cc + (c4 - Cc));
            else                    wv = *(const float4*)(Wt + (size_t)(k0 + k) * Cc + (c4 - 2 * Cc));
            *(float4*)&s.w[k][c4] = wv;
        }
        __syncthreads();

#pragma unroll 4
        for (int k = 0; k < KB; ++k) {
            unsigned long long ai[4], af[4];
#pragma unroll
            for (int i = 0; i < 4; i++) {
                float a0 = s_in[0][tm * 4 + i][k]; ai[i] = pack2(a0, a0);
                float a1 = s_in[1][tm * 4 + i][k]; af[i] = pack2(a1, a1);
            }
            ulonglong2 w0a = *(const ulonglong2*)&s.w[k][c0];
            ulonglong2 w0b = *(const ulonglong2*)&s.w[k][c0 + 4];
            ulonglong2 w1a = *(const ulonglong2*)&s.w[k][Cc + c0];
            ulonglong2 w1b = *(const ulonglong2*)&s.w[k][Cc + c0 + 4];
            ulonglong2 w2a = *(const ulonglong2*)&s.w[k][2 * Cc + c0];
            ulonglong2 w2b = *(const ulonglong2*)&s.w[k][2 * Cc + c0 + 4];
#pragma unroll
            for (int i = 0; i < 4; i++) {
                acc[i][0][0] = fma2(ai[i], w0a.x, acc[i][0][0]);
                acc[i][0][1] = fma2(ai[i], w0a.y, acc[i][0][1]);
                acc[i][0][2] = fma2(ai[i], w0b.x, acc[i][0][2]);
                acc[i][0][3] = fma2(ai[i], w0b.y, acc[i][0][3]);
                acc[i][1][0] = fma2(af[i], w1a.x, acc[i][1][0]);
                acc[i][1][1] = fma2(af[i], w1a.y, acc[i][1][1]);
                acc[i][1][2] = fma2(af[i], w1b.x, acc[i][1][2]);
                acc[i][1][3] = fma2(af[i], w1b.y, acc[i][1][3]);
                acc[i][2][0] = fma2(af[i], w2a.x, acc[i][2][0]);
                acc[i][2][1] = fma2(af[i], w2a.y, acc[i][2][1]);
                acc[i][2][2] = fma2(af[i], w2b.x, acc[i][2][2]);
                acc[i][2][3] = fma2(af[i], w2b.y, acc[i][2][3]);
            }
        }
    }
    __syncthreads();   // done reading s.w, about to overwrite with s.out

    // epilogue: nodewise = sigmoid(g1+g2+bg) * (t+bt)
    float bgv[8], btv[8];
#pragma unroll
    for (int j = 0; j < 8; j++) { bgv[j] = bg[c0 + j]; btv[j] = bt[c0 + j]; }
#pragma unroll
    for (int i = 0; i < 4; i++) {
        int m = tm * 4 + i;
#pragma unroll
        for (int j = 0; j < 4; j++) {
            float g1l, g1h, g2l, g2h, tl, th;
            unpack2(acc[i][0][j], g1l, g1h);
            unpack2(acc[i][1][j], g2l, g2h);
            unpack2(acc[i][2][j], tl, th);
            float xl = g1l + g2l + bgv[2 * j];
            float xh = g1h + g2h + bgv[2 * j + 1];
            float sl = 1.0f / (1.0f + __expf(-xl));
            float sh = 1.0f / (1.0f + __expf(-xh));
            s.out[m][c0 + 2 * j]     = sl * (tl + btv[2 * j]);
            s.out[m][c0 + 2 * j + 1] = sh * (th + btv[2 * j + 1]);
        }
    }
    __syncthreads();

    // sorted-id run-length reduction, one thread per channel
    if (tid < Cc) {
        const int c = tid;
        float run = 0.0f;
        int cur = s_gid[0];
#pragma unroll 4
        for (int n = 0; n < TILE_M; ++n) {
            int g = s_gid[n];
            if (g != cur) {
                atomicAdd(&g_readout[(size_t)cur * Cc + c], run);
                run = 0.0f; cur = g;
            }
            run += s.out[n][c];
        }
        atomicAdd(&g_readout[(size_t)cur * Cc + c], run);
    }
}

// ---------------- kernel 2: per-column BN stats -> scale/shift ----------------
__global__ __launch_bounds__(256)
void stats_kernel(const float* __restrict__ aux,
                  const float* __restrict__ gamma, const float* __restrict__ beta) {
    const int j = blockIdx.x;           // 0..159
    const int tid = threadIdx.x;
    float s = 0.0f, sq = 0.0f;
    for (int g = tid; g < NGg; g += 256) {
        float v = (j < Cc) ? g_readout[(size_t)g * Cc + j]
                           : aux[(size_t)g * Aa + (j - Cc)];
        s += v; sq += v * v;
    }
#pragma unroll
    for (int o = 16; o; o >>= 1) {
        s  += __shfl_xor_sync(0xffffffffu, s,  o);
        sq += __shfl_xor_sync(0xffffffffu, sq, o);
    }
    __shared__ float ws[8], wq[8];
    if ((tid & 31) == 0) { ws[tid >> 5] = s; wq[tid >> 5] = sq; }
    __syncthreads();
    if (tid == 0) {
        float S = 0.0f, Q = 0.0f;
#pragma unroll
        for (int i = 0; i < 8; i++) { S += ws[i]; Q += wq[i]; }
        float mean = S * (1.0f / NGg);
        float var  = Q * (1.0f / NGg) - mean * mean;
        float sc = gamma[j] * rsqrtf(var + BN_EPS);
        g_scale[j] = sc;
        g_shift[j] = beta[j] - mean * sc;
    }
}

// ---------------- kernel 3: hidden = relu(norm @ W1 + b1) ----------------
__global__ __launch_bounds__(256)
void mlp1_kernel(const float* __restrict__ aux,
                 const float* __restrict__ W1, const float* __restrict__ b1) {
    __shared__ float sA[64][33];
    __shared__ float sB[32][128];
    const int tid = threadIdx.x;
    const int tm = tid >> 4, tc = tid & 15;
    const int c0 = tc * 8;
    const int rowBase = blockIdx.x * 64;
    const int colBase = blockIdx.y * 128;

    unsigned long long acc[4][4];
#pragma unroll
    for (int i = 0; i < 4; i++)
#pragma unroll
        for (int j = 0; j < 4; j++) acc[i][j] = 0ULL;

    for (int chunk = 0; chunk < 5; ++chunk) {       // K = 160 = 5 * 32
        const int k0 = chunk * 32;
        __syncthreads();
#pragma unroll
        for (int it = 0; it < 2; ++it) {            // A tile 64x32, normalized on load
            int f = tid + it * 256;
            int n = f >> 3, q = f & 7;
            int j = k0 + 4 * q;
            float4 v;
            if (j < Cc) v = *(const float4*)(g_readout + (size_t)(rowBase + n) * Cc + j);
            else        v = *(const float4*)(aux + (size_t)(rowBase + n) * Aa + (j - Cc));
            float4 sc = *(const float4*)(g_scale + j);
            float4 sh = *(const float4*)(g_shift + j);
            sA[n][4 * q + 0] = fmaf(v.x, sc.x, sh.x);
            sA[n][4 * q + 1] = fmaf(v.y, sc.y, sh.y);
            sA[n][4 * q + 2] = fmaf(v.z, sc.z, sh.z);
            sA[n][4 * q + 3] = fmaf(v.w, sc.w, sh.w);
        }
#pragma unroll
        for (int it = 0; it < 4; ++it) {            // B tile 32x128
            int f = tid + it * 256;
            int k = f >> 5, c4 = (f & 31) * 4;
            *(float4*)&sB[k][c4] = *(const float4*)(W1 + (size_t)(k0 + k) * Gg + colBase + c4);
        }
        __syncthreads();
#pragma unroll 4
        for (int k = 0; k < 32; ++k) {
            unsigned long long av[4];
#pragma unroll
            for (int i = 0; i < 4; i++) { float a = sA[tm * 4 + i][k]; av[i] = pack2(a, a); }
            ulonglong2 wA = *(const ulonglong2*)&sB[k][c0];
            ulonglong2 wB = *(const ulonglong2*)&sB[k][c0 + 4];
#pragma unroll
            for (int i = 0; i < 4; i++) {
                acc[i][0] = fma2(av[i], wA.x, acc[i][0]);
                acc[i][1] = fma2(av[i], wA.y, acc[i][1]);
                acc[i][2] = fma2(av[i], wB.x, acc[i][2]);
                acc[i][3] = fma2(av[i], wB.y, acc[i][3]);
            }
        }
    }
    float bv[8];
#pragma unroll
    for (int j = 0; j < 8; j++) bv[j] = b1[colBase + c0 + j];
#pragma unroll
    for (int i = 0; i < 4; i++) {
        int r = rowBase + tm * 4 + i;
#pragma unroll
        for (int j = 0; j < 4; j++) {
            float lo, hi; unpack2(acc[i][j], lo, hi);
            lo = fmaxf(lo + bv[2 * j], 0.0f);
            hi = fmaxf(hi + bv[2 * j + 1], 0.0f);
            g_hidden[(size_t)r * Gg + colBase + c0 + 2 * j]     = lo;
            g_hidden[(size_t)r * Gg + colBase + c0 + 2 * j + 1] = hi;
        }
    }
}

// ---------------- kernel 4: logits = hidden @ W2 + b2 ----------------
__global__ __launch_bounds__(256)
void mlp2_kernel(const float* __restrict__ W2, const float* __restrict__ b2,
                 float* __restrict__ out) {
    __shared__ float sA[16][65];
    __shared__ float sB[64][128];
    const int tid = threadIdx.x;
    const int tm = tid >> 4, tc = tid & 15;
    const int c0 = tc * 8;
    const int rowBase = blockIdx.x * 16;

    unsigned long long acc[4] = {0ULL, 0ULL, 0ULL, 0ULL};
    for (int chunk = 0; chunk < 8; ++chunk) {       // K = 512 = 8 * 64
        const int k0 = chunk * 64;
        __syncthreads();
        {
            int n = tid >> 4, q = tid & 15;         // 16 rows x 16 float4 = 256 threads
            float4 v = *(const float4*)(g_hidden + (size_t)(rowBase + n) * Gg + k0 + 4 * q);
            sA[n][4 * q + 0] = v.x; sA[n][4 * q + 1] = v.y;
            sA[n][4 * q + 2] = v.z; sA[n][4 * q + 3] = v.w;
        }
#pragma unroll
        for (int it = 0; it < 8; ++it) {            // B tile 64x128
            int f = tid + it * 256;
            int k = f >> 5, c4 = (f & 31) * 4;
            *(float4*)&sB[k][c4] = *(const float4*)(W2 + (size_t)(k0 + k) * Cc + c4);
        }
        __syncthreads();
#pragma unroll 8
        for (int k = 0; k < 64; ++k) {
            float a = sA[tm][k];
            unsigned long long av = pack2(a, a);
            ulonglong2 wA = *(const ulonglong2*)&sB[k][c0];
            ulonglong2 wB = *(const ulonglong2*)&sB[k][c0 + 4];
            acc[0] = fma2(av, wA.x, acc[0]);
            acc[1] = fma2(av, wA.y, acc[1]);
            acc[2] = fma2(av, wB.x, acc[2]);
            acc[3] = fma2(av, wB.y, acc[3]);
        }
    }
#pragma unroll
    for (int j = 0; j < 4; j++) {
        float lo, hi; unpack2(acc[j], lo, hi);
        int r = rowBase + tm;
        out[(size_t)r * Cc + c0 + 2 * j]     = lo + b2[c0 + 2 * j];
        out[(size_t)r * Cc + c0 + 2 * j + 1] = hi + b2[c0 + 2 * j + 1];
    }
}

// ---------------- launch ----------------
extern "C" void kernel_launch(void* const* d_in, const int* in_sizes, int n_in,
                              void* d_out, int out_size) {
    (void)in_sizes; (void)out_size;
    const float* xinit = (const float*)d_in[0];
    const float* xfin  = (const float*)d_in[1];
    const float* aux   = (const float*)d_in[2];
    const int*   gid   = (const int*)d_in[3];
    // num_graphs may or may not be materialized as input #4
    const int wb = (n_in >= 15) ? 5 : 4;
    const float* Wg    = (const float*)d_in[wb + 0];
    const float* bg    = (const float*)d_in[wb + 1];
    const float* Wt    = (const float*)d_in[wb + 2];
    const float* bt    = (const float*)d_in[wb + 3];
    const float* gamma = (const float*)d_in[wb + 4];
    const float* beta  = (const float*)d_in[wb + 5];
    const float* W1    = (const float*)d_in[wb + 6];
    const float* b1    = (const float*)d_in[wb + 7];
    const float* W2    = (const float*)d_in[wb + 8];
    const float* b2    = (const float*)d_in[wb + 9];

    zero_kernel<<<(NGg * Cc + 255) / 256, 256>>>();
    node_kernel<<<Nn / TILE_M, 256>>>(xinit, xfin, gid, Wg, bg, Wt, bt);
    stats_kernel<<<CpA, 256>>>(aux, gamma, beta);
    mlp1_kernel<<<dim3(NGg / 64, Gg / 128), 256>>>(aux, W1, b1);
    mlp2_kernel<<<NGg / 16, 256>>>(W2, b2, (float*)d_out);
}

// round 3
// speedup vs baseline: 3.8111x; 3.8111x over previous
#include <cuda_runtime.h>
#include <cuda_bf16.h>
#include <cstdint>

// Problem constants
#define Nn   400000
#define Hh   256
#define Cc   128
#define Aa   32
#define Gg   512
#define NGg  1024
#define CpA  (Cc + Aa)          // 160
#define BN_EPS 1e-5f

#define Kt   512                // concat K: [init | fin]
#define Nt   256                // outputs: [gate(128) | t(128)]
#define Mt   128                // nodes per block
#define KC   64                 // K chunk
#define AROW (KC + 8)           // padded smem row, elems (72)

// ---------------- scratch (no allocations allowed) ----------------
__device__ float g_readout[NGg * Cc];            // segment sums  [1024,128]
__device__ float g_scale[CpA];
__device__ float g_shift[CpA];
__device__ float g_hidden[NGg * Gg];
__device__ __align__(16) __nv_bfloat16 g_Bhi[Nt * Kt];   // combined weights [n][k]
__device__ __align__(16) __nv_bfloat16 g_Blo[Nt * Kt];   // bf16 lo residual

// ---------------- PTX helpers ----------------
__device__ __forceinline__ uint32_t smem_u32(const void* p) {
    uint32_t a;
    asm("{ .reg .u64 t; cvta.to.shared.u64 t, %1; cvt.u32.u64 %0, t; }" : "=r"(a) : "l"(p));
    return a;
}
#define LDSM4(r, addr)                                                        \
    asm volatile("ldmatrix.sync.aligned.m8n8.x4.shared.b16 {%0,%1,%2,%3}, [%4];" \
        : "=r"((r)[0]), "=r"((r)[1]), "=r"((r)[2]), "=r"((r)[3]) : "r"(addr))

#define MMA(d, a, b0, b1)                                                     \
    asm volatile("mma.sync.aligned.m16n8k16.row.col.f32.bf16.bf16.f32 "       \
        "{%0,%1,%2,%3},{%4,%5,%6,%7},{%8,%9},{%0,%1,%2,%3};"                  \
        : "+f"((d)[0]), "+f"((d)[1]), "+f"((d)[2]), "+f"((d)[3])              \
        : "r"((a)[0]), "r"((a)[1]), "r"((a)[2]), "r"((a)[3]), "r"(b0), "r"(b1))

#define CP16(dst, src)                                                        \
    asm volatile("cp.async.cg.shared.global [%0], [%1], 16;" :: "r"(dst), "l"(src) : "memory")
#define CP_COMMIT() asm volatile("cp.async.commit_group;" ::: "memory")
#define CP_WAIT0()  asm volatile("cp.async.wait_group 0;" ::: "memory")

// ---------------- packed f32x2 helpers (MLP tail kernels) ----------------
__device__ __forceinline__ unsigned long long pack2(float lo, float hi) {
    unsigned long long r;
    asm("mov.b64 %0, {%1, %2};" : "=l"(r) : "f"(lo), "f"(hi));
    return r;
}
__device__ __forceinline__ void unpack2(unsigned long long v, float& lo, float& hi) {
    asm("mov.b64 {%0, %1}, %2;" : "=f"(lo), "=f"(hi) : "l"(v));
}
__device__ __forceinline__ unsigned long long fma2(unsigned long long a,
                                                   unsigned long long b,
                                                   unsigned long long c) {
    unsigned long long d;
    asm("fma.rn.f32x2 %0, %1, %2, %3;" : "=l"(d) : "l"(a), "l"(b), "l"(c));
    return d;
}

// ---------------- kernel: zero segment-sum buffer ----------------
__global__ void zero_kernel() {
    int i = blockIdx.x * blockDim.x + threadIdx.x;
    if (i < NGg * Cc) g_readout[i] = 0.0f;
}

// ---------------- kernel: build combined bf16 hi/lo weight matrix ----------------
// B[n][k]: n<128 -> Wg[k][n]; n>=128 -> (k>=256 ? Wt[k-256][n-128] : 0)
__global__ void prep_kernel(const float* __restrict__ Wg, const float* __restrict__ Wt) {
    int idx = blockIdx.x * 256 + threadIdx.x;     // 0 .. 256*512-1
    int n = idx >> 9, k = idx & 511;
    float w;
    if (n < 128)          w = Wg[(size_t)k * Cc + n];
    else if (k >= 256)    w = Wt[(size_t)(k - 256) * Cc + (n - 128)];
    else                  w = 0.0f;
    __nv_bfloat16 hi = __float2bfloat16(w);
    __nv_bfloat16 lo = __float2bfloat16(w - __bfloat162float(hi));
    g_Bhi[idx] = hi;
    g_Blo[idx] = lo;
}

// ---------------- node kernel: HMMA GEMM + gate + segment-sum ----------------
// dynamic smem, per stage:
//   A_hi [128][72] bf16 (18432B) | A_lo (18432B) | B_hi [256][72] bf16 (36864B) | B_lo
#define OFF_A_HI  0
#define OFF_A_LO  18432
#define OFF_B_HI  36864
#define OFF_B_LO  73728
#define STG       110592
#define SMEM_DYN  (2 * STG)      // 221184
#define OUTROW    132            // fp32 out tile row stride (elems)

__device__ __forceinline__ void ldgA(const float* __restrict__ X, int nodeBase,
                                     int kloc, int tid, float4* aR) {
#pragma unroll
    for (int it = 0; it < 4; ++it) {
        int f = tid + it * 512;
        int m = f >> 4, q = f & 15;
        aR[it] = *(const float4*)(X + (size_t)(nodeBase + m) * Hh + kloc + 4 * q);
    }
}

__device__ __forceinline__ void stsA(char* stage, int tid, const float4* aR) {
#pragma unroll
    for (int it = 0; it < 4; ++it) {
        int f = tid + it * 512;
        int m = f >> 4, q = f & 15;
        float4 v = aR[it];
        __nv_bfloat162 h0 = __float22bfloat162_rn(make_float2(v.x, v.y));
        __nv_bfloat162 h1 = __float22bfloat162_rn(make_float2(v.z, v.w));
        __nv_bfloat162 l0 = __float22bfloat162_rn(make_float2(
            v.x - __low2float(h0), v.y - __high2float(h0)));
        __nv_bfloat162 l1 = __float22bfloat162_rn(make_float2(
            v.z - __low2float(h1), v.w - __high2float(h1)));
        uint32_t off = m * (AROW * 2) + q * 8;
        uint2 H; H.x = *(uint32_t*)&h0; H.y = *(uint32_t*)&h1;
        uint2 L; L.x = *(uint32_t*)&l0; L.y = *(uint32_t*)&l1;
        *(uint2*)(stage + OFF_A_HI + off) = H;
        *(uint2*)(stage + OFF_A_LO + off) = L;
    }
}

__device__ __forceinline__ void cpB(uint32_t stB_hi, uint32_t stB_lo,
                                    int kbytes, int tid) {
#pragma unroll
    for (int it = 0; it < 4; ++it) {
        int f = tid + it * 512;
        int n = f >> 3, q = f & 7;
        uint32_t dst = n * (AROW * 2) + q * 16;
        CP16(stB_hi + dst, (const char*)g_Bhi + (size_t)n * (Kt * 2) + kbytes + q * 16);
        CP16(stB_lo + dst, (const char*)g_Blo + (size_t)n * (Kt * 2) + kbytes + q * 16);
    }
    CP_COMMIT();
}

__global__ __launch_bounds__(512, 1)
void node_kernel(const float* __restrict__ xinit, const float* __restrict__ xfin,
                 const int* __restrict__ gids,
                 const float* __restrict__ bg, const float* __restrict__ bt) {
    extern __shared__ char smem[];
    __shared__ int s_gid[Mt];
    const uint32_t sbase = smem_u32(smem);
    const int tid = threadIdx.x;
    const int wid = tid >> 5;
    const int l = tid & 31;
    const int wm = wid & 3;          // 0..3 -> 32 rows each
    const int wn = wid >> 2;         // 0..3 -> 64 cols each
    const int nodeBase = blockIdx.x * Mt;

    if (tid < Mt) s_gid[tid] = gids[nodeBase + tid];

    // ldmatrix per-thread offsets (bytes)
    const uint32_t aOff = ((wm * 32 + (l & 15)) * AROW + ((l >> 4) * 8)) * 2;
    const uint32_t bOff = ((wn * 64 + ((l >> 4) & 1) * 8 + (l & 7)) * AROW +
                           ((l >> 3) & 1) * 8) * 2 + OFF_B_HI;

    float acc[2][8][4];
#pragma unroll
    for (int i = 0; i < 2; i++)
#pragma unroll
        for (int j = 0; j < 8; j++)
#pragma unroll
            for (int p = 0; p < 4; p++) acc[i][j][p] = 0.0f;

    float4 aR[4];

    // prologue: chunk 0 into stage 0
    ldgA(xinit, nodeBase, 0, tid, aR);
    cpB(sbase + OFF_B_HI, sbase + OFF_B_LO, 0, tid);
    stsA(smem, tid, aR);
    CP_WAIT0();
    __syncthreads();

    for (int i = 0; i < 8; ++i) {
        const int cur = i & 1;
        const uint32_t stg = sbase + (uint32_t)cur * STG;
        const bool pf = (i < 7);
        if (pf) {
            const int c = i + 1;
            const float* X = (c < 4) ? xinit : xfin;
            ldgA(X, nodeBase, (c & 3) * KC, tid, aR);
            cpB(sbase + (1 - cur) * STG + OFF_B_HI,
                sbase + (1 - cur) * STG + OFF_B_LO, c * KC * 2, tid);
        }

#pragma unroll
        for (int ks = 0; ks < 4; ++ks) {
            const uint32_t aA = stg + aOff + ks * 32;
            uint32_t ah0[4], ah1[4], al0[4], al1[4];
            LDSM4(ah0, aA);
            LDSM4(ah1, aA + 16 * AROW * 2);
            LDSM4(al0, aA + (OFF_A_LO - OFF_A_HI));
            LDSM4(al1, aA + (OFF_A_LO - OFF_A_HI) + 16 * AROW * 2);
#pragma unroll
            for (int np = 0; np < 4; ++np) {
                const uint32_t bA = stg + bOff + np * (16 * AROW * 2) + ks * 32;
                uint32_t bh[4], bl[4];
                LDSM4(bh, bA);
                LDSM4(bl, bA + (OFF_B_LO - OFF_B_HI));
                MMA(acc[0][2 * np],     ah0, bh[0], bh[1]);
                MMA(acc[0][2 * np],     ah0, bl[0], bl[1]);
                MMA(acc[0][2 * np],     al0, bh[0], bh[1]);
                MMA(acc[0][2 * np + 1], ah0, bh[2], bh[3]);
                MMA(acc[0][2 * np + 1], ah0, bl[2], bl[3]);
                MMA(acc[0][2 * np + 1], al0, bh[2], bh[3]);
                MMA(acc[1][2 * np],     ah1, bh[0], bh[1]);
                MMA(acc[1][2 * np],     ah1, bl[0], bl[1]);
                MMA(acc[1][2 * np],     al1, bh[0], bh[1]);
                MMA(acc[1][2 * np + 1], ah1, bh[2], bh[3]);
                MMA(acc[1][2 * np + 1], ah1, bl[2], bl[3]);
                MMA(acc[1][2 * np + 1], al1, bh[2], bh[3]);
            }
        }

        if (pf) {
            stsA(smem + (1 - cur) * STG, tid, aR);
            CP_WAIT0();
        }
        __syncthreads();
    }

    // ---- epilogue ----
    float* sOut = (float*)smem;          // [128][OUTROW] fp32, aliases stage 0
    const int r = l >> 2;
    const int cq = (l & 3) * 2;

    if (wn < 2) {        // gate warps: store raw gate logits
#pragma unroll
        for (int mt = 0; mt < 2; ++mt)
#pragma unroll
            for (int nt = 0; nt < 8; ++nt) {
                int m = wm * 32 + mt * 16 + r;
                int c = wn * 64 + nt * 8 + cq;
                float* p = sOut + m * OUTROW + c;
                p[0] = acc[mt][nt][0];
                p[1] = acc[mt][nt][1];
                p[8 * OUTROW] = acc[mt][nt][2];
                p[8 * OUTROW + 1] = acc[mt][nt][3];
            }
    }
    __syncthreads();
    if (wn >= 2) {       // t warps: out = sigmoid(g + bg) * (t + bt), in place
#pragma unroll
        for (int mt = 0; mt < 2; ++mt)
#pragma unroll
            for (int nt = 0; nt < 8; ++nt) {
                int m = wm * 32 + mt * 16 + r;
                int ct = (wn - 2) * 64 + nt * 8 + cq;
                float bg0 = bg[ct], bg1 = bg[ct + 1];
                float bt0 = bt[ct], bt1 = bt[ct + 1];
                float* p = sOut + m * OUTROW + ct;
                float g0 = p[0], g1 = p[1];
                float g2 = p[8 * OUTROW], g3 = p[8 * OUTROW + 1];
                p[0] = (acc[mt][nt][0] + bt0) / (1.0f + __expf(-(g0 + bg0)));
                p[1] = (acc[mt][nt][1] + bt1) / (1.0f + __expf(-(g1 + bg1)));
                p[8 * OUTROW]     = (acc[mt][nt][2] + bt0) / (1.0f + __expf(-(g2 + bg0)));
                p[8 * OUTROW + 1] = (acc[mt][nt][3] + bt1) / (1.0f + __expf(-(g3 + bg1)));
            }
    }
    __syncthreads();

    // sorted-id run-length segment sum: 4 threads per channel, 32 nodes each
    {
        const int c = tid & 127;
        const int n0 = (tid >> 7) * 32;
        float run = 0.0f;
        int cur = s_gid[n0];
        for (int n = n0; n < n0 + 32; ++n) {
            int g = s_gid[n];
            if (g != cur) {
                atomicAdd(&g_readout[(size_t)cur * Cc + c], run);
                run = 0.0f; cur = g;
            }
            run += sOut[n * OUTROW + c];
        }
        atomicAdd(&g_readout[(size_t)cur * Cc + c], run);
    }
}

// ---------------- kernel: per-column BN stats -> scale/shift ----------------
__global__ __launch_bounds__(256)
void stats_kernel(const float* __restrict__ aux,
                  const float* __restrict__ gamma, const float* __restrict__ beta) {
    const int j = blockIdx.x;
    const int tid = threadIdx.x;
    float s = 0.0f, sq = 0.0f;
    for (int g = tid; g < NGg; g += 256) {
        float v = (j < Cc) ? g_readout[(size_t)g * Cc + j]
                           : aux[(size_t)g * Aa + (j - Cc)];
        s += v; sq += v * v;
    }
#pragma unroll
    for (int o = 16; o; o >>= 1) {
        s  += __shfl_xor_sync(0xffffffffu, s,  o);
        sq += __shfl_xor_sync(0xffffffffu, sq, o);
    }
    __shared__ float ws[8], wq[8];
    if ((tid & 31) == 0) { ws[tid >> 5] = s; wq[tid >> 5] = sq; }
    __syncthreads();
    if (tid == 0) {
        float S = 0.0f, Q = 0.0f;
#pragma unroll
        for (int i = 0; i < 8; i++) { S += ws[i]; Q += wq[i]; }
        float mean = S * (1.0f / NGg);
        float var  = Q * (1.0f / NGg) - mean * mean;
        float sc = gamma[j] * rsqrtf(var + BN_EPS);
        g_scale[j] = sc;
        g_shift[j] = beta[j] - mean * sc;
    }
}

// ---------------- kernel: hidden = relu(norm @ W1 + b1) ----------------
__global__ __launch_bounds__(256)
void mlp1_kernel(const float* __restrict__ aux,
                 const float* __restrict__ W1, const float* __restrict__ b1) {
    __shared__ float sA[64][33];
    __shared__ float sB[32][128];
    const int tid = threadIdx.x;
    const int tm = tid >> 4, tc = tid & 15;
    const int c0 = tc * 8;
    const int rowBase = blockIdx.x * 64;
    const int colBase = blockIdx.y * 128;

    unsigned long long acc[4][4];
#pragma unroll
    for (int i = 0; i < 4; i++)
#pragma unroll
        for (int j = 0; j < 4; j++) acc[i][j] = 0ULL;

    for (int chunk = 0; chunk < 5; ++chunk) {       // K = 160
        const int k0 = chunk * 32;
        __syncthreads();
#pragma unroll
        for (int it = 0; it < 2; ++it) {
            int f = tid + it * 256;
            int n = f >> 3, q = f & 7;
            int j = k0 + 4 * q;
            float4 v;
            if (j < Cc) v = *(const float4*)(g_readout + (size_t)(rowBase + n) * Cc + j);
            else        v = *(const float4*)(aux + (size_t)(rowBase + n) * Aa + (j - Cc));
            float4 sc = *(const float4*)(g_scale + j);
            float4 sh = *(const float4*)(g_shift + j);
            sA[n][4 * q + 0] = fmaf(v.x, sc.x, sh.x);
            sA[n][4 * q + 1] = fmaf(v.y, sc.y, sh.y);
            sA[n][4 * q + 2] = fmaf(v.z, sc.z, sh.z);
            sA[n][4 * q + 3] = fmaf(v.w, sc.w, sh.w);
        }
#pragma unroll
        for (int it = 0; it < 4; ++it) {
            int f = tid + it * 256;
            int k = f >> 5, c4 = (f & 31) * 4;
            *(float4*)&sB[k][c4] = *(const float4*)(W1 + (size_t)(k0 + k) * Gg + colBase + c4);
        }
        __syncthreads();
#pragma unroll 4
        for (int k = 0; k < 32; ++k) {
            unsigned long long av[4];
#pragma unroll
            for (int i = 0; i < 4; i++) { float a = sA[tm * 4 + i][k]; av[i] = pack2(a, a); }
            ulonglong2 wA = *(const ulonglong2*)&sB[k][c0];
            ulonglong2 wB = *(const ulonglong2*)&sB[k][c0 + 4];
#pragma unroll
            for (int i = 0; i < 4; i++) {
                acc[i][0] = fma2(av[i], wA.x, acc[i][0]);
                acc[i][1] = fma2(av[i], wA.y, acc[i][1]);
                acc[i][2] = fma2(av[i], wB.x, acc[i][2]);
                acc[i][3] = fma2(av[i], wB.y, acc[i][3]);
            }
        }
    }
    float bv[8];
#pragma unroll
    for (int j = 0; j < 8; j++) bv[j] = b1[colBase + c0 + j];
#pragma unroll
    for (int i = 0; i < 4; i++) {
        int r = rowBase + tm * 4 + i;
#pragma unroll
        for (int j = 0; j < 4; j++) {
            float lo, hi; unpack2(acc[i][j], lo, hi);
            lo = fmaxf(lo + bv[2 * j], 0.0f);
            hi = fmaxf(hi + bv[2 * j + 1], 0.0f);
            g_hidden[(size_t)r * Gg + colBase + c0 + 2 * j]     = lo;
            g_hidden[(size_t)r * Gg + colBase + c0 + 2 * j + 1] = hi;
        }
    }
}

// ---------------- kernel: logits = hidden @ W2 + b2 ----------------
__global__ __launch_bounds__(256)
void mlp2_kernel(const float* __restrict__ W2, const float* __restrict__ b2,
                 float* __restrict__ out) {
    __shared__ float sA[16][65];
    __shared__ float sB[64][128];
    const int tid = threadIdx.x;
    const int tm = tid >> 4, tc = tid & 15;
    const int c0 = tc * 8;
    const int rowBase = blockIdx.x * 16;

    unsigned long long acc[4] = {0ULL, 0ULL, 0ULL, 0ULL};
    for (int chunk = 0; chunk < 8; ++chunk) {       // K = 512
        const int k0 = chunk * 64;
        __syncthreads();
        {
            int n = tid >> 4, q = tid & 15;
            float4 v = *(const float4*)(g_hidden + (size_t)(rowBase + n) * Gg + k0 + 4 * q);
            sA[n][4 * q + 0] = v.x; sA[n][4 * q + 1] = v.y;
            sA[n][4 * q + 2] = v.z; sA[n][4 * q + 3] = v.w;
        }
#pragma unroll
        for (int it = 0; it < 8; ++it) {
            int f = tid + it * 256;
            int k = f >> 5, c4 = (f & 31) * 4;
            *(float4*)&sB[k][c4] = *(const float4*)(W2 + (size_t)(k0 + k) * Cc + c4);
        }
        __syncthreads();
#pragma unroll 8
        for (int k = 0; k < 64; ++k) {
            float a = sA[tm][k];
            unsigned long long av = pack2(a, a);
            ulonglong2 wA = *(const ulonglong2*)&sB[k][c0];
            ulonglong2 wB = *(const ulonglong2*)&sB[k][c0 + 4];
            acc[0] = fma2(av, wA.x, acc[0]);
            acc[1] = fma2(av, wA.y, acc[1]);
            acc[2] = fma2(av, wB.x, acc[2]);
            acc[3] = fma2(av, wB.y, acc[3]);
        }
    }
#pragma unroll
    for (int j = 0; j < 4; j++) {
        float lo, hi; unpack2(acc[j], lo, hi);
        int r = rowBase + tm;
        out[(size_t)r * Cc + c0 + 2 * j]     = lo + b2[c0 + 2 * j];
        out[(size_t)r * Cc + c0 + 2 * j + 1] = hi + b2[c0 + 2 * j + 1];
    }
}

// ---------------- launch ----------------
extern "C" void kernel_launch(void* const* d_in, const int* in_sizes, int n_in,
                              void* d_out, int out_size) {
    (void)in_sizes; (void)out_size;
    const float* xinit = (const float*)d_in[0];
    const float* xfin  = (const float*)d_in[1];
    const float* aux   = (const float*)d_in[2];
    const int*   gid   = (const int*)d_in[3];
    const int wb = (n_in >= 15) ? 5 : 4;
    const float* Wg    = (const float*)d_in[wb + 0];
    const float* bg    = (const float*)d_in[wb + 1];
    const float* Wt    = (const float*)d_in[wb + 2];
    const float* bt    = (const float*)d_in[wb + 3];
    const float* gamma = (const float*)d_in[wb + 4];
    const float* beta  = (const float*)d_in[wb + 5];
    const float* W1    = (const float*)d_in[wb + 6];
    const float* b1    = (const float*)d_in[wb + 7];
    const float* W2    = (const float*)d_in[wb + 8];
    const float* b2    = (const float*)d_in[wb + 9];

    cudaFuncSetAttribute(node_kernel, cudaFuncAttributeMaxDynamicSharedMemorySize, SMEM_DYN);

    prep_kernel<<<(Nt * Kt) / 256, 256>>>(Wg, Wt);
    zero_kernel<<<(NGg * Cc + 255) / 256, 256>>>();
    node_kernel<<<Nn / Mt, 512, SMEM_DYN>>>(xinit, xfin, gid, bg, bt);
    stats_kernel<<<CpA, 256>>>(aux, gamma, beta);
    mlp1_kernel<<<dim3(NGg / 64, Gg / 128), 256>>>(aux, W1, b1);
    mlp2_kernel<<<NGg / 16, 256>>>(W2, b2, (float*)d_out);
}

// round 4
// speedup vs baseline: 4.2363x; 1.1116x over previous
#include <cuda_runtime.h>
#include <cuda_bf16.h>
#include <cstdint>

// Problem constants
#define Nn   400000
#define Hh   256
#define Cc   128
#define Aa   32
#define Gg   512
#define NGg  1024
#define CpA  (Cc + Aa)          // 160
#define BN_EPS 1e-5f

#define Kt   512                // concat K: [init | fin]
#define Nt   256                // outputs: [gate(128) | t(128)]
#define Mt   128                // nodes per block
#define KC   64                 // K chunk
#define AROW (KC + 8)           // padded smem row, elems (72)

// ---------------- scratch (no allocations allowed) ----------------
__device__ float g_readout[NGg * Cc];            // segment sums  [1024,128]
__device__ float g_scale[CpA];
__device__ float g_shift[CpA];
__device__ float g_hidden[NGg * Gg];
__device__ __align__(16) __nv_bfloat16 g_Bhi[Nt * Kt];   // combined weights [n][k]
__device__ __align__(16) __nv_bfloat16 g_Blo[Nt * Kt];   // bf16 lo residual

// ---------------- PTX helpers ----------------
__device__ __forceinline__ uint32_t smem_u32(const void* p) {
    uint32_t a;
    asm("{ .reg .u64 t; cvta.to.shared.u64 t, %1; cvt.u32.u64 %0, t; }" : "=r"(a) : "l"(p));
    return a;
}
#define LDSM4(r, addr)                                                        \
    asm volatile("ldmatrix.sync.aligned.m8n8.x4.shared.b16 {%0,%1,%2,%3}, [%4];" \
        : "=r"((r)[0]), "=r"((r)[1]), "=r"((r)[2]), "=r"((r)[3]) : "r"(addr))

#define MMA(d, a, b0, b1)                                                     \
    asm volatile("mma.sync.aligned.m16n8k16.row.col.f32.bf16.bf16.f32 "       \
        "{%0,%1,%2,%3},{%4,%5,%6,%7},{%8,%9},{%0,%1,%2,%3};"                  \
        : "+f"((d)[0]), "+f"((d)[1]), "+f"((d)[2]), "+f"((d)[3])              \
        : "r"((a)[0]), "r"((a)[1]), "r"((a)[2]), "r"((a)[3]), "r"(b0), "r"(b1))

#define CP16(dst, src)                                                        \
    asm volatile("cp.async.cg.shared.global [%0], [%1], 16;" :: "r"(dst), "l"(src) : "memory")
#define CP_COMMIT() asm volatile("cp.async.commit_group;" ::: "memory")
#define CP_WAIT0()  asm volatile("cp.async.wait_group 0;" ::: "memory")

// ---------------- packed f32x2 helpers (MLP tail kernels) ----------------
__device__ __forceinline__ unsigned long long pack2(float lo, float hi) {
    unsigned long long r;
    asm("mov.b64 %0, {%1, %2};" : "=l"(r) : "f"(lo), "f"(hi));
    return r;
}
__device__ __forceinline__ void unpack2(unsigned long long v, float& lo, float& hi) {
    asm("mov.b64 {%0, %1}, %2;" : "=f"(lo), "=f"(hi) : "l"(v));
}
__device__ __forceinline__ unsigned long long fma2(unsigned long long a,
                                                   unsigned long long b,
                                                   unsigned long long c) {
    unsigned long long d;
    asm("fma.rn.f32x2 %0, %1, %2, %3;" : "=l"(d) : "l"(a), "l"(b), "l"(c));
    return d;
}

// ---------------- kernel: build combined weights + zero readout ----------------
// B[n][k]: n<128 -> Wg[k][n]; n>=128 -> (k>=256 ? Wt[k-256][n-128] : 0)
// grid is exactly 512 blocks * 256 threads = 131072 = NGg*Cc -> also zero g_readout
__global__ void prep_kernel(const float* __restrict__ Wg, const float* __restrict__ Wt) {
    int idx = blockIdx.x * 256 + threadIdx.x;     // 0 .. 131071
    int n = idx >> 9, k = idx & 511;
    float w;
    if (n < 128)          w = Wg[(size_t)k * Cc + n];
    else if (k >= 256)    w = Wt[(size_t)(k - 256) * Cc + (n - 128)];
    else                  w = 0.0f;
    __nv_bfloat16 hi = __float2bfloat16(w);
    __nv_bfloat16 lo = __float2bfloat16(w - __bfloat162float(hi));
    g_Bhi[idx] = hi;
    g_Blo[idx] = lo;
    g_readout[idx] = 0.0f;
}

// ---------------- node kernel: HMMA GEMM + gate + segment-sum ----------------
// dynamic smem, per stage:
//   A_hi [128][72] bf16 (18432B) | A_lo (18432B) | B_hi [256][72] bf16 (36864B) | B_lo
#define OFF_A_HI  0
#define OFF_A_LO  18432
#define OFF_B_HI  36864
#define OFF_B_LO  73728
#define STG       110592
#define SMEM_DYN  (2 * STG)      // 221184
#define OUTROW    132            // fp32 out tile row stride (elems)

__device__ __forceinline__ void ldgA(const float* __restrict__ X, int nodeBase,
                                     int kloc, int tid, float4* aR) {
#pragma unroll
    for (int it = 0; it < 4; ++it) {
        int f = tid + it * 512;
        int m = f >> 4, q = f & 15;
        aR[it] = *(const float4*)(X + (size_t)(nodeBase + m) * Hh + kloc + 4 * q);
    }
}

__device__ __forceinline__ void stsA(char* stage, int tid, const float4* aR) {
#pragma unroll
    for (int it = 0; it < 4; ++it) {
        int f = tid + it * 512;
        int m = f >> 4, q = f & 15;
        float4 v = aR[it];
        __nv_bfloat162 h0 = __float22bfloat162_rn(make_float2(v.x, v.y));
        __nv_bfloat162 h1 = __float22bfloat162_rn(make_float2(v.z, v.w));
        __nv_bfloat162 l0 = __float22bfloat162_rn(make_float2(
            v.x - __low2float(h0), v.y - __high2float(h0)));
        __nv_bfloat162 l1 = __float22bfloat162_rn(make_float2(
            v.z - __low2float(h1), v.w - __high2float(h1)));
        uint32_t off = m * (AROW * 2) + q * 8;
        uint2 H; H.x = *(uint32_t*)&h0; H.y = *(uint32_t*)&h1;
        uint2 L; L.x = *(uint32_t*)&l0; L.y = *(uint32_t*)&l1;
        *(uint2*)(stage + OFF_A_HI + off) = H;
        *(uint2*)(stage + OFF_A_LO + off) = L;
    }
}

// copy B rows [0, nrows) for this K chunk; nrows is 128 (gate-only) or 256
__device__ __forceinline__ void cpB(uint32_t stB_hi, uint32_t stB_lo,
                                    int kbytes, int tid, int nrows) {
    const int iters = nrows >> 6;                // 2 or 4
    for (int it = 0; it < iters; ++it) {
        int f = tid + it * 512;
        int n = f >> 3, q = f & 7;
        uint32_t dst = n * (AROW * 2) + q * 16;
        CP16(stB_hi + dst, (const char*)g_Bhi + (size_t)n * (Kt * 2) + kbytes + q * 16);
        CP16(stB_lo + dst, (const char*)g_Blo + (size_t)n * (Kt * 2) + kbytes + q * 16);
    }
    CP_COMMIT();
}

__global__ __launch_bounds__(512, 1)
void node_kernel(const float* __restrict__ xinit, const float* __restrict__ xfin,
                 const int* __restrict__ gids,
                 const float* __restrict__ bg, const float* __restrict__ bt) {
    extern __shared__ char smem[];
    __shared__ int s_gid[Mt];
    const uint32_t sbase = smem_u32(smem);
    const int tid = threadIdx.x;
    const int wid = tid >> 5;
    const int l = tid & 31;
    const int wm = wid & 3;          // 0..3 -> 32 rows each
    const int wn = wid >> 2;         // 0..3 -> 64 cols each
    const int nodeBase = blockIdx.x * Mt;

    if (tid < Mt) s_gid[tid] = gids[nodeBase + tid];

    // ldmatrix per-thread offsets (bytes)
    const uint32_t aOff = ((wm * 32 + (l & 15)) * AROW + ((l >> 4) * 8)) * 2;
    const uint32_t bOff = ((wn * 64 + ((l >> 4) & 1) * 8 + (l & 7)) * AROW +
                           ((l >> 3) & 1) * 8) * 2 + OFF_B_HI;

    float acc[2][8][4];
#pragma unroll
    for (int i = 0; i < 2; i++)
#pragma unroll
        for (int j = 0; j < 8; j++)
#pragma unroll
            for (int p = 0; p < 4; p++) acc[i][j][p] = 0.0f;

    float4 aR[4];

    // prologue: chunk 0 into stage 0 (gate-only -> 128 B rows)
    ldgA(xinit, nodeBase, 0, tid, aR);
    cpB(sbase + OFF_B_HI, sbase + OFF_B_LO, 0, tid, 128);
    stsA(smem, tid, aR);
    CP_WAIT0();
    __syncthreads();

    for (int i = 0; i < 8; ++i) {
        const int cur = i & 1;
        const uint32_t stg = sbase + (uint32_t)cur * STG;
        const bool pf = (i < 7);
        if (pf) {
            const int c = i + 1;
            const float* X = (c < 4) ? xinit : xfin;
            ldgA(X, nodeBase, (c & 3) * KC, tid, aR);
            cpB(sbase + (1 - cur) * STG + OFF_B_HI,
                sbase + (1 - cur) * STG + OFF_B_LO, c * KC * 2, tid,
                (c < 4) ? 128 : 256);
        }

        // chunks 0-3 multiply against the init half, where all t-columns of B
        // are structurally zero -> t warps (wn >= 2) skip their MMA block.
        if (i >= 4 || wn < 2) {
#pragma unroll
            for (int ks = 0; ks < 4; ++ks) {
                const uint32_t aA = stg + aOff + ks * 32;
                uint32_t ah0[4], ah1[4], al0[4], al1[4];
                LDSM4(ah0, aA);
                LDSM4(ah1, aA + 16 * AROW * 2);
                LDSM4(al0, aA + (OFF_A_LO - OFF_A_HI));
                LDSM4(al1, aA + (OFF_A_LO - OFF_A_HI) + 16 * AROW * 2);
#pragma unroll
                for (int np = 0; np < 4; ++np) {
                    const uint32_t bA = stg + bOff + np * (16 * AROW * 2) + ks * 32;
                    uint32_t bh[4], bl[4];
                    LDSM4(bh, bA);
                    LDSM4(bl, bA + (OFF_B_LO - OFF_B_HI));
                    MMA(acc[0][2 * np],     ah0, bh[0], bh[1]);
                    MMA(acc[0][2 * np],     ah0, bl[0], bl[1]);
                    MMA(acc[0][2 * np],     al0, bh[0], bh[1]);
                    MMA(acc[0][2 * np + 1], ah0, bh[2], bh[3]);
                    MMA(acc[0][2 * np + 1], ah0, bl[2], bl[3]);
                    MMA(acc[0][2 * np + 1], al0, bh[2], bh[3]);
                    MMA(acc[1][2 * np],     ah1, bh[0], bh[1]);
                    MMA(acc[1][2 * np],     ah1, bl[0], bl[1]);
                    MMA(acc[1][2 * np],     al1, bh[0], bh[1]);
                    MMA(acc[1][2 * np + 1], ah1, bh[2], bh[3]);
                    MMA(acc[1][2 * np + 1], ah1, bl[2], bl[3]);
                    MMA(acc[1][2 * np + 1], al1, bh[2], bh[3]);
                }
            }
        }

        if (pf) {
            stsA(smem + (1 - cur) * STG, tid, aR);
            CP_WAIT0();
        }
        __syncthreads();
    }

    // ---- epilogue ----
    float* sOut = (float*)smem;          // [128][OUTROW] fp32, aliases stage 0
    const int r = l >> 2;
    const int cq = (l & 3) * 2;

    if (wn < 2) {        // gate warps: store raw gate logits
#pragma unroll
        for (int mt = 0; mt < 2; ++mt)
#pragma unroll
            for (int nt = 0; nt < 8; ++nt) {
                int m = wm * 32 + mt * 16 + r;
                int c = wn * 64 + nt * 8 + cq;
                float* p = sOut + m * OUTROW + c;
                p[0] = acc[mt][nt][0];
                p[1] = acc[mt][nt][1];
                p[8 * OUTROW] = acc[mt][nt][2];
                p[8 * OUTROW + 1] = acc[mt][nt][3];
            }
    }
    __syncthreads();
    if (wn >= 2) {       // t warps: out = sigmoid(g + bg) * (t + bt), in place
#pragma unroll
        for (int mt = 0; mt < 2; ++mt)
#pragma unroll
            for (int nt = 0; nt < 8; ++nt) {
                int m = wm * 32 + mt * 16 + r;
                int ct = (wn - 2) * 64 + nt * 8 + cq;
                float bg0 = bg[ct], bg1 = bg[ct + 1];
                float bt0 = bt[ct], bt1 = bt[ct + 1];
                float* p = sOut + m * OUTROW + ct;
                float g0 = p[0], g1 = p[1];
                float g2 = p[8 * OUTROW], g3 = p[8 * OUTROW + 1];
                p[0] = (acc[mt][nt][0] + bt0) / (1.0f + __expf(-(g0 + bg0)));
                p[1] = (acc[mt][nt][1] + bt1) / (1.0f + __expf(-(g1 + bg1)));
                p[8 * OUTROW]     = (acc[mt][nt][2] + bt0) / (1.0f + __expf(-(g2 + bg0)));
                p[8 * OUTROW + 1] = (acc[mt][nt][3] + bt1) / (1.0f + __expf(-(g3 + bg1)));
            }
    }
    __syncthreads();

    // sorted-id run-length segment sum: 4 threads per channel, 32 nodes each
    {
        const int c = tid & 127;
        const int n0 = (tid >> 7) * 32;
        float run = 0.0f;
        int cur = s_gid[n0];
        for (int n = n0; n < n0 + 32; ++n) {
            int g = s_gid[n];
            if (g != cur) {
                atomicAdd(&g_readout[(size_t)cur * Cc + c], run);
                run = 0.0f; cur = g;
            }
            run += sOut[n * OUTROW + c];
        }
        atomicAdd(&g_readout[(size_t)cur * Cc + c], run);
    }
}

// ---------------- kernel: per-column BN stats -> scale/shift ----------------
__global__ __launch_bounds__(256)
void stats_kernel(const float* __restrict__ aux,
                  const float* __restrict__ gamma, const float* __restrict__ beta) {
    const int j = blockIdx.x;
    const int tid = threadIdx.x;
    float s = 0.0f, sq = 0.0f;
    for (int g = tid; g < NGg; g += 256) {
        float v = (j < Cc) ? g_readout[(size_t)g * Cc + j]
                           : aux[(size_t)g * Aa + (j - Cc)];
        s += v; sq += v * v;
    }
#pragma unroll
    for (int o = 16; o; o >>= 1) {
        s  += __shfl_xor_sync(0xffffffffu, s,  o);
        sq += __shfl_xor_sync(0xffffffffu, sq, o);
    }
    __shared__ float ws[8], wq[8];
    if ((tid & 31) == 0) { ws[tid >> 5] = s; wq[tid >> 5] = sq; }
    __syncthreads();
    if (tid == 0) {
        float S = 0.0f, Q = 0.0f;
#pragma unroll
        for (int i = 0; i < 8; i++) { S += ws[i]; Q += wq[i]; }
        float mean = S * (1.0f / NGg);
        float var  = Q * (1.0f / NGg) - mean * mean;
        float sc = gamma[j] * rsqrtf(var + BN_EPS);
        g_scale[j] = sc;
        g_shift[j] = beta[j] - mean * sc;
    }
}

// ---------------- kernel: hidden = relu(norm @ W1 + b1) ----------------
__global__ __launch_bounds__(256)
void mlp1_kernel(const float* __restrict__ aux,
                 const float* __restrict__ W1, const float* __restrict__ b1) {
    __shared__ float sA[64][33];
    __shared__ float sB[32][128];
    const int tid = threadIdx.x;
    const int tm = tid >> 4, tc = tid & 15;
    const int c0 = tc * 8;
    const int rowBase = blockIdx.x * 64;
    const int colBase = blockIdx.y * 128;

    unsigned long long acc[4][4];
#pragma unroll
    for (int i = 0; i < 4; i++)
#pragma unroll
        for (int j = 0; j < 4; j++) acc[i][j] = 0ULL;

    for (int chunk = 0; chunk < 5; ++chunk) {       // K = 160
        const int k0 = chunk * 32;
        __syncthreads();
#pragma unroll
        for (int it = 0; it < 2; ++it) {
            int f = tid + it * 256;
            int n = f >> 3, q = f & 7;
            int j = k0 + 4 * q;
            float4 v;
            if (j < Cc) v = *(const float4*)(g_readout + (size_t)(rowBase + n) * Cc + j);
            else        v = *(const float4*)(aux + (size_t)(rowBase + n) * Aa + (j - Cc));
            float4 sc = *(const float4*)(g_scale + j);
            float4 sh = *(const float4*)(g_shift + j);
            sA[n][4 * q + 0] = fmaf(v.x, sc.x, sh.x);
            sA[n][4 * q + 1] = fmaf(v.y, sc.y, sh.y);
            sA[n][4 * q + 2] = fmaf(v.z, sc.z, sh.z);
            sA[n][4 * q + 3] = fmaf(v.w, sc.w, sh.w);
        }
#pragma unroll
        for (int it = 0; it < 4; ++it) {
            int f = tid + it * 256;
            int k = f >> 5, c4 = (f & 31) * 4;
            *(float4*)&sB[k][c4] = *(const float4*)(W1 + (size_t)(k0 + k) * Gg + colBase + c4);
        }
        __syncthreads();
#pragma unroll 4
        for (int k = 0; k < 32; ++k) {
            unsigned long long av[4];
#pragma unroll
            for (int i = 0; i < 4; i++) { float a = sA[tm * 4 + i][k]; av[i] = pack2(a, a); }
            ulonglong2 wA = *(const ulonglong2*)&sB[k][c0];
            ulonglong2 wB = *(const ulonglong2*)&sB[k][c0 + 4];
#pragma unroll
            for (int i = 0; i < 4; i++) {
                acc[i][0] = fma2(av[i], wA.x, acc[i][0]);
                acc[i][1] = fma2(av[i], wA.y, acc[i][1]);
                acc[i][2] = fma2(av[i], wB.x, acc[i][2]);
                acc[i][3] = fma2(av[i], wB.y, acc[i][3]);
            }
        }
    }
    float bv[8];
#pragma unroll
    for (int j = 0; j < 8; j++) bv[j] = b1[colBase + c0 + j];
#pragma unroll
    for (int i = 0; i < 4; i++) {
        int r = rowBase + tm * 4 + i;
#pragma unroll
        for (int j = 0; j < 4; j++) {
            float lo, hi; unpack2(acc[i][j], lo, hi);
            lo = fmaxf(lo + bv[2 * j], 0.0f);
            hi = fmaxf(hi + bv[2 * j + 1], 0.0f);
            g_hidden[(size_t)r * Gg + colBase + c0 + 2 * j]     = lo;
            g_hidden[(size_t)r * Gg + colBase + c0 + 2 * j + 1] = hi;
        }
    }
}

// ---------------- kernel: logits = hidden @ W2 + b2 ----------------
__global__ __launch_bounds__(256)
void mlp2_kernel(const float* __restrict__ W2, const float* __restrict__ b2,
                 float* __restrict__ out) {
    __shared__ float sA[16][65];
    __shared__ float sB[64][128];
    const int tid = threadIdx.x;
    const int tm = tid >> 4, tc = tid & 15;
    const int c0 = tc * 8;
    const int rowBase = blockIdx.x * 16;

    unsigned long long acc[4] = {0ULL, 0ULL, 0ULL, 0ULL};
    for (int chunk = 0; chunk < 8; ++chunk) {       // K = 512
        const int k0 = chunk * 64;
        __syncthreads();
        {
            int n = tid >> 4, q = tid & 15;
            float4 v = *(const float4*)(g_hidden + (size_t)(rowBase + n) * Gg + k0 + 4 * q);
            sA[n][4 * q + 0] = v.x; sA[n][4 * q + 1] = v.y;
            sA[n][4 * q + 2] = v.z; sA[n][4 * q + 3] = v.w;
        }
#pragma unroll
        for (int it = 0; it < 8; ++it) {
            int f = tid + it * 256;
            int k = f >> 5, c4 = (f & 31) * 4;
            *(float4*)&sB[k][c4] = *(const float4*)(W2 + (size_t)(k0 + k) * Cc + c4);
        }
        __syncthreads();
#pragma unroll 8
        for (int k = 0; k < 64; ++k) {
            float a = sA[tm][k];
            unsigned long long av = pack2(a, a);
            ulonglong2 wA = *(const ulonglong2*)&sB[k][c0];
            ulonglong2 wB = *(const ulonglong2*)&sB[k][c0 + 4];
            acc[0] = fma2(av, wA.x, acc[0]);
            acc[1] = fma2(av, wA.y, acc[1]);
            acc[2] = fma2(av, wB.x, acc[2]);
            acc[3] = fma2(av, wB.y, acc[3]);
        }
    }
#pragma unroll
    for (int j = 0; j < 4; j++) {
        float lo, hi; unpack2(acc[j], lo, hi);
        int r = rowBase + tm;
        out[(size_t)r * Cc + c0 + 2 * j]     = lo + b2[c0 + 2 * j];
        out[(size_t)r * Cc + c0 + 2 * j + 1] = hi + b2[c0 + 2 * j + 1];
    }
}

// ---------------- launch ----------------
extern "C" void kernel_launch(void* const* d_in, const int* in_sizes, int n_in,
                              void* d_out, int out_size) {
    (void)in_sizes; (void)out_size;
    const float* xinit = (const float*)d_in[0];
    const float* xfin  = (const float*)d_in[1];
    const float* aux   = (const float*)d_in[2];
    const int*   gid   = (const int*)d_in[3];
    const int wb = (n_in >= 15) ? 5 : 4;
    const float* Wg    = (const float*)d_in[wb + 0];
    const float* bg    = (const float*)d_in[wb + 1];
    const float* Wt    = (const float*)d_in[wb + 2];
    const float* bt    = (const float*)d_in[wb + 3];
    const float* gamma = (const float*)d_in[wb + 4];
    const float* beta  = (const float*)d_in[wb + 5];
    const float* W1    = (const float*)d_in[wb + 6];
    const float* b1    = (const float*)d_in[wb + 7];
    const float* W2    = (const float*)d_in[wb + 8];
    const float* b2    = (const float*)d_in[wb + 9];

    cudaFuncSetAttribute(node_kernel, cudaFuncAttributeMaxDynamicSharedMemorySize, SMEM_DYN);

    prep_kernel<<<(Nt * Kt) / 256, 256>>>(Wg, Wt);   // also zeroes g_readout
    node_kernel<<<Nn / Mt, 512, SMEM_DYN>>>(xinit, xfin, gid, bg, bt);
    stats_kernel<<<CpA, 256>>>(aux, gamma, beta);
    mlp1_kernel<<<dim3(NGg / 64, Gg / 128), 256>>>(aux, W1, b1);
    mlp2_kernel<<<NGg / 16, 256>>>(W2, b2, (float*)d_out);
}

// round 5
// speedup vs baseline: 4.8498x; 1.1448x over previous
#include <cuda_runtime.h>
#include <cuda_bf16.h>
#include <cuda_fp16.h>
#include <cstdint>

// Problem constants
#define Nn   400000
#define Hh   256
#define Cc   128
#define Aa   32
#define Gg   512
#define NGg  1024
#define CpA  (Cc + Aa)          // 160
#define BN_EPS 1e-5f

#define Kt   512                // concat K: [init | fin]
#define Nt   256                // outputs: [gate(128) | t(128)]
#define Mt   128                // nodes per block
#define KC   64                 // K chunk
#define AROW (KC + 8)           // padded smem row, elems (72)

// ---------------- scratch (no allocations allowed) ----------------
__device__ float g_readout[NGg * Cc];            // segment sums  [1024,128]
__device__ float g_scale[CpA];
__device__ float g_shift[CpA];
__device__ float g_hidden[NGg * Gg];
__device__ __align__(16) __half g_Bh[Nt * Kt];   // combined weights [n][k], fp16

// ---------------- PTX helpers ----------------
__device__ __forceinline__ uint32_t smem_u32(const void* p) {
    uint32_t a;
    asm("{ .reg .u64 t; cvta.to.shared.u64 t, %1; cvt.u32.u64 %0, t; }" : "=r"(a) : "l"(p));
    return a;
}
#define LDSM4(r, addr)                                                        \
    asm volatile("ldmatrix.sync.aligned.m8n8.x4.shared.b16 {%0,%1,%2,%3}, [%4];" \
        : "=r"((r)[0]), "=r"((r)[1]), "=r"((r)[2]), "=r"((r)[3]) : "r"(addr))

#define MMA(d, a, b0, b1)                                                     \
    asm volatile("mma.sync.aligned.m16n8k16.row.col.f32.f16.f16.f32 "         \
        "{%0,%1,%2,%3},{%4,%5,%6,%7},{%8,%9},{%0,%1,%2,%3};"                  \
        : "+f"((d)[0]), "+f"((d)[1]), "+f"((d)[2]), "+f"((d)[3])              \
        : "r"((a)[0]), "r"((a)[1]), "r"((a)[2]), "r"((a)[3]), "r"(b0), "r"(b1))

#define CP16(dst, src)                                                        \
    asm volatile("cp.async.cg.shared.global [%0], [%1], 16;" :: "r"(dst), "l"(src) : "memory")
#define CP_COMMIT() asm volatile("cp.async.commit_group;" ::: "memory")
#define CP_WAIT0()  asm volatile("cp.async.wait_group 0;" ::: "memory")

// ---------------- packed f32x2 helpers (MLP tail kernels) ----------------
__device__ __forceinline__ unsigned long long pack2(float lo, float hi) {
    unsigned long long r;
    asm("mov.b64 %0, {%1, %2};" : "=l"(r) : "f"(lo), "f"(hi));
    return r;
}
__device__ __forceinline__ void unpack2(unsigned long long v, float& lo, float& hi) {
    asm("mov.b64 {%0, %1}, %2;" : "=f"(lo), "=f"(hi) : "l"(v));
}
__device__ __forceinline__ unsigned long long fma2(unsigned long long a,
                                                   unsigned long long b,
                                                   unsigned long long c) {
    unsigned long long d;
    asm("fma.rn.f32x2 %0, %1, %2, %3;" : "=l"(d) : "l"(a), "l"(b), "l"(c));
    return d;
}

// ---------------- kernel: build combined fp16 weights + zero readout ----------------
// B[n][k]: n<128 -> Wg[k][n]; n>=128 -> (k>=256 ? Wt[k-256][n-128] : 0)
// grid 512 blocks * 256 threads = 131072 = NGg*Cc -> also zeroes g_readout
__global__ void prep_kernel(const float* __restrict__ Wg, const float* __restrict__ Wt) {
    int idx = blockIdx.x * 256 + threadIdx.x;     // 0 .. 131071
    int n = idx >> 9, k = idx & 511;
    float w;
    if (n < 128)          w = Wg[(size_t)k * Cc + n];
    else if (k >= 256)    w = Wt[(size_t)(k - 256) * Cc + (n - 128)];
    else                  w = 0.0f;
    g_Bh[idx] = __float2half_rn(w);
    g_readout[idx] = 0.0f;
}

// ---------------- node kernel: HMMA GEMM + gate + segment-sum ----------------
// dynamic smem, 3 stages of:
//   A_hi [128][72] fp16 (18432B) | A_lo (18432B) | B [256][72] fp16 (36864B)
#define OFF_A_LO  18432
#define OFF_B     36864
#define STG       73728
#define SMEM_DYN  (3 * STG)      // 221184
#define OUTROW    132            // fp32 out tile row stride (elems)

__device__ __forceinline__ void ldgA(const float* __restrict__ X, int nodeBase,
                                     int kloc, int tid, float4* aR) {
#pragma unroll
    for (int it = 0; it < 4; ++it) {
        int f = tid + it * 512;
        int m = f >> 4, q = f & 15;
        aR[it] = *(const float4*)(X + (size_t)(nodeBase + m) * Hh + kloc + 4 * q);
    }
}

__device__ __forceinline__ void stsA(char* stage, int tid, const float4* aR) {
#pragma unroll
    for (int it = 0; it < 4; ++it) {
        int f = tid + it * 512;
        int m = f >> 4, q = f & 15;
        float4 v = aR[it];
        __half2 h0 = __floats2half2_rn(v.x, v.y);
        __half2 h1 = __floats2half2_rn(v.z, v.w);
        __half2 l0 = __floats2half2_rn(v.x - __low2float(h0), v.y - __high2float(h0));
        __half2 l1 = __floats2half2_rn(v.z - __low2float(h1), v.w - __high2float(h1));
        uint32_t off = m * (AROW * 2) + q * 8;
        uint2 H; H.x = *(uint32_t*)&h0; H.y = *(uint32_t*)&h1;
        uint2 L; L.x = *(uint32_t*)&l0; L.y = *(uint32_t*)&l1;
        *(uint2*)(stage + off) = H;
        *(uint2*)(stage + OFF_A_LO + off) = L;
    }
}

// copy B rows [0, nrows) for one K chunk; nrows is 128 (gate-only) or 256
__device__ __forceinline__ void cpB(uint32_t stB, int kbytes, int tid, int nrows) {
    const int iters = nrows >> 6;                // 2 or 4
    for (int it = 0; it < iters; ++it) {
        int f = tid + it * 512;
        int n = f >> 3, q = f & 7;
        uint32_t dst = n * (AROW * 2) + q * 16;
        CP16(stB + dst, (const char*)g_Bh + (size_t)n * (Kt * 2) + kbytes + q * 16);
    }
    CP_COMMIT();
}

__global__ __launch_bounds__(512, 1)
void node_kernel(const float* __restrict__ xinit, const float* __restrict__ xfin,
                 const int* __restrict__ gids,
                 const float* __restrict__ bg, const float* __restrict__ bt) {
    extern __shared__ char smem[];
    __shared__ int s_gid[Mt];
    const uint32_t sbase = smem_u32(smem);
    const int tid = threadIdx.x;
    const int wid = tid >> 5;
    const int l = tid & 31;
    const int wm = wid & 3;          // 0..3 -> 32 rows each
    const int wn = wid >> 2;         // 0..3 -> 64 cols each
    const int nodeBase = blockIdx.x * Mt;

    if (tid < Mt) s_gid[tid] = gids[nodeBase + tid];

    // ldmatrix per-thread offsets (bytes)
    const uint32_t aOff = ((wm * 32 + (l & 15)) * AROW + ((l >> 4) * 8)) * 2;
    const uint32_t bOff = ((wn * 64 + ((l >> 4) & 1) * 8 + (l & 7)) * AROW +
                           ((l >> 3) & 1) * 8) * 2 + OFF_B;

    float acc[2][8][4];
#pragma unroll
    for (int i = 0; i < 2; i++)
#pragma unroll
        for (int j = 0; j < 8; j++)
#pragma unroll
            for (int p = 0; p < 4; p++) acc[i][j][p] = 0.0f;

    float4 rA[2][4];

    // prologue: chunks 0,1 into stages 0,1; chunk 2 LDG'd into regs
    ldgA(xinit, nodeBase, 0, tid, rA[0]);
    ldgA(xinit, nodeBase, KC, tid, rA[1]);
    cpB(sbase + OFF_B, 0, tid, 128);             // B chunk 0 (gate rows only)
    stsA(smem, tid, rA[0]);
    stsA(smem + STG, tid, rA[1]);
    ldgA(xinit, nodeBase, 2 * KC, tid, rA[0]);   // chunk 2 pending
    CP_WAIT0();
    __syncthreads();

    for (int j = 0; j < 8; ++j) {
        const uint32_t stg = sbase + (uint32_t)(j % 3) * STG;
        // LDG chunk j+3 (3 ahead)
        if (j + 3 < 8) {
            const int c = j + 3;
            const float* X = (c < 4) ? xinit : xfin;
            ldgA(X, nodeBase, (c & 3) * KC, tid, rA[(j + 1) & 1]);
        }
        // B for chunk j+1 (1 ahead, L2-resident)
        if (j + 1 < 8) {
            const int c = j + 1;
            cpB(sbase + (uint32_t)((j + 1) % 3) * STG + OFF_B, c * KC * 2, tid,
                (c < 4) ? 128 : 256);
        }

        // chunks 0-3 hit the init half, where all t-columns of B are zero:
        // t warps (wn >= 2) skip their LDSM+MMA block entirely.
        if (j >= 4 || wn < 2) {
#pragma unroll
            for (int ks = 0; ks < 4; ++ks) {
                const uint32_t aA = stg + aOff + ks * 32;
                uint32_t ah0[4], ah1[4], al0[4], al1[4];
                LDSM4(ah0, aA);
                LDSM4(ah1, aA + 16 * AROW * 2);
                LDSM4(al0, aA + OFF_A_LO);
                LDSM4(al1, aA + OFF_A_LO + 16 * AROW * 2);
#pragma unroll
                for (int np = 0; np < 4; ++np) {
                    const uint32_t bA = stg + bOff + np * (16 * AROW * 2) + ks * 32;
                    uint32_t bh[4];
                    LDSM4(bh, bA);
                    MMA(acc[0][2 * np],     ah0, bh[0], bh[1]);
                    MMA(acc[0][2 * np],     al0, bh[0], bh[1]);
                    MMA(acc[0][2 * np + 1], ah0, bh[2], bh[3]);
                    MMA(acc[0][2 * np + 1], al0, bh[2], bh[3]);
                    MMA(acc[1][2 * np],     ah1, bh[0], bh[1]);
                    MMA(acc[1][2 * np],     al1, bh[0], bh[1]);
                    MMA(acc[1][2 * np + 1], ah1, bh[2], bh[3]);
                    MMA(acc[1][2 * np + 1], al1, bh[2], bh[3]);
                }
            }
        }

        // STS chunk j+2 (LDG'd one full iteration ago -> ~2 MMA blocks of slack)
        if (j + 2 < 8) stsA(smem + ((j + 2) % 3) * STG, tid, rA[j & 1]);
        if (j + 1 < 8) CP_WAIT0();
        __syncthreads();
    }

    // ---- epilogue ----
    float* sOut = (float*)smem;          // [128][OUTROW] fp32, aliases stages
    const int r = l >> 2;
    const int cq = (l & 3) * 2;

    if (wn < 2) {        // gate warps: store raw gate logits
#pragma unroll
        for (int mt = 0; mt < 2; ++mt)
#pragma unroll
            for (int nt = 0; nt < 8; ++nt) {
                int m = wm * 32 + mt * 16 + r;
                int c = wn * 64 + nt * 8 + cq;
                float* p = sOut + m * OUTROW + c;
                p[0] = acc[mt][nt][0];
                p[1] = acc[mt][nt][1];
                p[8 * OUTROW] = acc[mt][nt][2];
                p[8 * OUTROW + 1] = acc[mt][nt][3];
            }
    }
    __syncthreads();
    if (wn >= 2) {       // t warps: out = sigmoid(g + bg) * (t + bt), in place
#pragma unroll
        for (int mt = 0; mt < 2; ++mt)
#pragma unroll
            for (int nt = 0; nt < 8; ++nt) {
                int m = wm * 32 + mt * 16 + r;
                int ct = (wn - 2) * 64 + nt * 8 + cq;
                float bg0 = bg[ct], bg1 = bg[ct + 1];
                float bt0 = bt[ct], bt1 = bt[ct + 1];
                float* p = sOut + m * OUTROW + ct;
                float g0 = p[0], g1 = p[1];
                float g2 = p[8 * OUTROW], g3 = p[8 * OUTROW + 1];
                p[0] = (acc[mt][nt][0] + bt0) / (1.0f + __expf(-(g0 + bg0)));
                p[1] = (acc[mt][nt][1] + bt1) / (1.0f + __expf(-(g1 + bg1)));
                p[8 * OUTROW]     = (acc[mt][nt][2] + bt0) / (1.0f + __expf(-(g2 + bg0)));
                p[8 * OUTROW + 1] = (acc[mt][nt][3] + bt1) / (1.0f + __expf(-(g3 + bg1)));
            }
    }
    __syncthreads();

    // sorted-id run-length segment sum: 4 threads per channel, 32 nodes each
    {
        const int c = tid & 127;
        const int n0 = (tid >> 7) * 32;
        float run = 0.0f;
        int cur = s_gid[n0];
        for (int n = n0; n < n0 + 32; ++n) {
            int g = s_gid[n];
            if (g != cur) {
                atomicAdd(&g_readout[(size_t)cur * Cc + c], run);
                run = 0.0f; cur = g;
            }
            run += sOut[n * OUTROW + c];
        }
        atomicAdd(&g_readout[(size_t)cur * Cc + c], run);
    }
}

// ---------------- kernel: per-column BN stats -> scale/shift ----------------
__global__ __launch_bounds__(256)
void stats_kernel(const float* __restrict__ aux,
                  const float* __restrict__ gamma, const float* __restrict__ beta) {
    const int j = blockIdx.x;
    const int tid = threadIdx.x;
    float s = 0.0f, sq = 0.0f;
    for (int g = tid; g < NGg; g += 256) {
        float v = (j < Cc) ? g_readout[(size_t)g * Cc + j]
                           : aux[(size_t)g * Aa + (j - Cc)];
        s += v; sq += v * v;
    }
#pragma unroll
    for (int o = 16; o; o >>= 1) {
        s  += __shfl_xor_sync(0xffffffffu, s,  o);
        sq += __shfl_xor_sync(0xffffffffu, sq, o);
    }
    __shared__ float ws[8], wq[8];
    if ((tid & 31) == 0) { ws[tid >> 5] = s; wq[tid >> 5] = sq; }
    __syncthreads();
    if (tid == 0) {
        float S = 0.0f, Q = 0.0f;
#pragma unroll
        for (int i = 0; i < 8; i++) { S += ws[i]; Q += wq[i]; }
        float mean = S * (1.0f / NGg);
        float var  = Q * (1.0f / NGg) - mean * mean;
        float sc = gamma[j] * rsqrtf(var + BN_EPS);
        g_scale[j] = sc;
        g_shift[j] = beta[j] - mean * sc;
    }
}

// ---------------- kernel: hidden = relu(norm @ W1 + b1) ----------------
__global__ __launch_bounds__(256)
void mlp1_kernel(const float* __restrict__ aux,
                 const float* __restrict__ W1, const float* __restrict__ b1) {
    __shared__ float sA[64][33];
    __shared__ float sB[32][128];
    const int tid = threadIdx.x;
    const int tm = tid >> 4, tc = tid & 15;
    const int c0 = tc * 8;
    const int rowBase = blockIdx.x * 64;
    const int colBase = blockIdx.y * 128;

    unsigned long long acc[4][4];
#pragma unroll
    for (int i = 0; i < 4; i++)
#pragma unroll
        for (int j = 0; j < 4; j++) acc[i][j] = 0ULL;

    for (int chunk = 0; chunk < 5; ++chunk) {       // K = 160
        const int k0 = chunk * 32;
        __syncthreads();
#pragma unroll
        for (int it = 0; it < 2; ++it) {
            int f = tid + it * 256;
            int n = f >> 3, q = f & 7;
            int j = k0 + 4 * q;
            float4 v;
            if (j < Cc) v = *(const float4*)(g_readout + (size_t)(rowBase + n) * Cc + j);
            else        v = *(const float4*)(aux + (size_t)(rowBase + n) * Aa + (j - Cc));
            float4 sc = *(const float4*)(g_scale + j);
            float4 sh = *(const float4*)(g_shift + j);
            sA[n][4 * q + 0] = fmaf(v.x, sc.x, sh.x);
            sA[n][4 * q + 1] = fmaf(v.y, sc.y, sh.y);
            sA[n][4 * q + 2] = fmaf(v.z, sc.z, sh.z);
            sA[n][4 * q + 3] = fmaf(v.w, sc.w, sh.w);
        }
#pragma unroll
        for (int it = 0; it < 4; ++it) {
            int f = tid + it * 256;
            int k = f >> 5, c4 = (f & 31) * 4;
            *(float4*)&sB[k][c4] = *(const float4*)(W1 + (size_t)(k0 + k) * Gg + colBase + c4);
        }
        __syncthreads();
#pragma unroll 4
        for (int k = 0; k < 32; ++k) {
            unsigned long long av[4];
#pragma unroll
            for (int i = 0; i < 4; i++) { float a = sA[tm * 4 + i][k]; av[i] = pack2(a, a); }
            ulonglong2 wA = *(const ulonglong2*)&sB[k][c0];
            ulonglong2 wB = *(const ulonglong2*)&sB[k][c0 + 4];
#pragma unroll
            for (int i = 0; i < 4; i++) {
                acc[i][0] = fma2(av[i], wA.x, acc[i][0]);
                acc[i][1] = fma2(av[i], wA.y, acc[i][1]);
                acc[i][2] = fma2(av[i], wB.x, acc[i][2]);
                acc[i][3] = fma2(av[i], wB.y, acc[i][3]);
            }
        }
    }
    float bv[8];
#pragma unroll
    for (int j = 0; j < 8; j++) bv[j] = b1[colBase + c0 + j];
#pragma unroll
    for (int i = 0; i < 4; i++) {
        int r = rowBase + tm * 4 + i;
#pragma unroll
        for (int j = 0; j < 4; j++) {
            float lo, hi; unpack2(acc[i][j], lo, hi);
            lo = fmaxf(lo + bv[2 * j], 0.0f);
            hi = fmaxf(hi + bv[2 * j + 1], 0.0f);
            g_hidden[(size_t)r * Gg + colBase + c0 + 2 * j]     = lo;
            g_hidden[(size_t)r * Gg + colBase + c0 + 2 * j + 1] = hi;
        }
    }
}

// ---------------- kernel: logits = hidden @ W2 + b2 ----------------
__global__ __launch_bounds__(256)
void mlp2_kernel(const float* __restrict__ W2, const float* __restrict__ b2,
                 float* __restrict__ out) {
    __shared__ float sA[16][65];
    __shared__ float sB[64][128];
    const int tid = threadIdx.x;
    const int tm = tid >> 4, tc = tid & 15;
    const int c0 = tc * 8;
    const int rowBase = blockIdx.x * 16;

    unsigned long long acc[4] = {0ULL, 0ULL, 0ULL, 0ULL};
    for (int chunk = 0; chunk < 8; ++chunk) {       // K = 512
        const int k0 = chunk * 64;
        __syncthreads();
        {
            int n = tid >> 4, q = tid & 15;
            float4 v = *(const float4*)(g_hidden + (size_t)(rowBase + n) * Gg + k0 + 4 * q);
            sA[n][4 * q + 0] = v.x; sA[n][4 * q + 1] = v.y;
            sA[n][4 * q + 2] = v.z; sA[n][4 * q + 3] = v.w;
        }
#pragma unroll
        for (int it = 0; it < 8; ++it) {
            int f = tid + it * 256;
            int k = f >> 5, c4 = (f & 31) * 4;
            *(float4*)&sB[k][c4] = *(const float4*)(W2 + (size_t)(k0 + k) * Cc + c4);
        }
        __syncthreads();
#pragma unroll 8
        for (int k = 0; k < 64; ++k) {
            float a = sA[tm][k];
            unsigned long long av = pack2(a, a);
            ulonglong2 wA = *(const ulonglong2*)&sB[k][c0];
            ulonglong2 wB = *(const ulonglong2*)&sB[k][c0 + 4];
            acc[0] = fma2(av, wA.x, acc[0]);
            acc[1] = fma2(av, wA.y, acc[1]);
            acc[2] = fma2(av, wB.x, acc[2]);
            acc[3] = fma2(av, wB.y, acc[3]);
        }
    }
#pragma unroll
    for (int j = 0; j < 4; j++) {
        float lo, hi; unpack2(acc[j], lo, hi);
        int r = rowBase + tm;
        out[(size_t)r * Cc + c0 + 2 * j]     = lo + b2[c0 + 2 * j];
        out[(size_t)r * Cc + c0 + 2 * j + 1] = hi + b2[c0 + 2 * j + 1];
    }
}

// ---------------- launch ----------------
extern "C" void kernel_launch(void* const* d_in, const int* in_sizes, int n_in,
                              void* d_out, int out_size) {
    (void)in_sizes; (void)out_size;
    const float* xinit = (const float*)d_in[0];
    const float* xfin  = (const float*)d_in[1];
    const float* aux   = (const float*)d_in[2];
    const int*   gid   = (const int*)d_in[3];
    const int wb = (n_in >= 15) ? 5 : 4;
    const float* Wg    = (const float*)d_in[wb + 0];
    const float* bg    = (const float*)d_in[wb + 1];
    const float* Wt    = (const float*)d_in[wb + 2];
    const float* bt    = (const float*)d_in[wb + 3];
    const float* gamma = (const float*)d_in[wb + 4];
    const float* beta  = (const float*)d_in[wb + 5];
    const float* W1    = (const float*)d_in[wb + 6];
    const float* b1    = (const float*)d_in[wb + 7];
    const float* W2    = (const float*)d_in[wb + 8];
    const float* b2    = (const float*)d_in[wb + 9];

    cudaFuncSetAttribute(node_kernel, cudaFuncAttributeMaxDynamicSharedMemorySize, SMEM_DYN);

    prep_kernel<<<(Nt * Kt) / 256, 256>>>(Wg, Wt);   // also zeroes g_readout
    node_kernel<<<Nn / Mt, 512, SMEM_DYN>>>(xinit, xfin, gid, bg, bt);
    stats_kernel<<<CpA, 256>>>(aux, gamma, beta);
    mlp1_kernel<<<dim3(NGg / 64, Gg / 128), 256>>>(aux, W1, b1);
    mlp2_kernel<<<NGg / 16, 256>>>(W2, b2, (float*)d_out);
}

// round 6
// speedup vs baseline: 7.3500x; 1.5155x over previous
#include <cuda_runtime.h>
#include <cuda_bf16.h>
#include <cuda_fp16.h>
#include <cstdint>

// Problem constants
#define Nn   400000
#define Hh   256
#define Cc   128
#define Aa   32
#define Gg   512
#define NGg  1024
#define CpA  (Cc + Aa)          // 160
#define BN_EPS 1e-5f

#define Kt   512                // concat K: [init | fin]
#define Nt   256                // outputs: [gate(128) | t(128)]
#define Mt   128                // nodes per block
#define KC   64                 // K chunk
#define AROW (KC + 8)           // padded smem row, elems (72)

// ---------------- scratch (no allocations allowed) ----------------
__device__ float g_readout[NGg * Cc];            // segment sums  [1024,128]
__device__ float g_scale[CpA];
__device__ float g_shift[CpA];
__device__ float g_hidden[NGg * Gg];
__device__ __align__(16) __half g_Bh[Nt * Kt];   // combined weights [n][k], fp16

// ---------------- PTX helpers ----------------
__device__ __forceinline__ uint32_t smem_u32(const void* p) {
    uint32_t a;
    asm("{ .reg .u64 t; cvta.to.shared.u64 t, %1; cvt.u32.u64 %0, t; }" : "=r"(a) : "l"(p));
    return a;
}
#define LDSM4(r, addr)                                                        \
    asm volatile("ldmatrix.sync.aligned.m8n8.x4.shared.b16 {%0,%1,%2,%3}, [%4];" \
        : "=r"((r)[0]), "=r"((r)[1]), "=r"((r)[2]), "=r"((r)[3]) : "r"(addr))

#define MMA(d, a, b0, b1)                                                     \
    asm volatile("mma.sync.aligned.m16n8k16.row.col.f32.f16.f16.f32 "         \
        "{%0,%1,%2,%3},{%4,%5,%6,%7},{%8,%9},{%0,%1,%2,%3};"                  \
        : "+f"((d)[0]), "+f"((d)[1]), "+f"((d)[2]), "+f"((d)[3])              \
        : "r"((a)[0]), "r"((a)[1]), "r"((a)[2]), "r"((a)[3]), "r"(b0), "r"(b1))

#define CP16(dst, src)                                                        \
    asm volatile("cp.async.cg.shared.global [%0], [%1], 16;" :: "r"(dst), "l"(src) : "memory")
#define CP_COMMIT() asm volatile("cp.async.commit_group;" ::: "memory")
#define CP_WAIT0()  asm volatile("cp.async.wait_group 0;" ::: "memory")
#define CP_WAIT1()  asm volatile("cp.async.wait_group 1;" ::: "memory")

// ---------------- packed f32x2 helpers (MLP tail kernels) ----------------
__device__ __forceinline__ unsigned long long pack2(float lo, float hi) {
    unsigned long long r;
    asm("mov.b64 %0, {%1, %2};" : "=l"(r) : "f"(lo), "f"(hi));
    return r;
}
__device__ __forceinline__ void unpack2(unsigned long long v, float& lo, float& hi) {
    asm("mov.b64 {%0, %1}, %2;" : "=f"(lo), "=f"(hi) : "l"(v));
}
__device__ __forceinline__ unsigned long long fma2(unsigned long long a,
                                                   unsigned long long b,
                                                   unsigned long long c) {
    unsigned long long d;
    asm("fma.rn.f32x2 %0, %1, %2, %3;" : "=l"(d) : "l"(a), "l"(b), "l"(c));
    return d;
}

// ---------------- kernel: build combined fp16 weights + zero readout ----------------
// B[n][k]: n<128 -> Wg[k][n]; n>=128 -> (k>=256 ? Wt[k-256][n-128] : 0)
__global__ void prep_kernel(const float* __restrict__ Wg, const float* __restrict__ Wt) {
    int idx = blockIdx.x * 256 + threadIdx.x;     // 0 .. 131071
    int n = idx >> 9, k = idx & 511;
    float w;
    if (n < 128)          w = Wg[(size_t)k * Cc + n];
    else if (k >= 256)    w = Wt[(size_t)(k - 256) * Cc + (n - 128)];
    else                  w = 0.0f;
    g_Bh[idx] = __float2half_rn(w);
    g_readout[idx] = 0.0f;
}

// ---------------- node kernel: HMMA GEMM + gate + segment-sum ----------------
// dynamic smem, 4 stages of:
//   A [128][72] fp16 (18432B) | B [256][72] fp16 (36864B)   = 55296B/stage
#define OFF_B     18432
#define STG       55296
#define SMEM_DYN  (4 * STG)      // 221184
#define OUTROW    132            // fp32 out tile row stride (elems)

__device__ __forceinline__ void ldgA(const float* __restrict__ X, int nodeBase,
                                     int kloc, int tid, float4* aR) {
#pragma unroll
    for (int it = 0; it < 4; ++it) {
        int f = tid + it * 512;
        int m = f >> 4, q = f & 15;
        aR[it] = *(const float4*)(X + (size_t)(nodeBase + m) * Hh + kloc + 4 * q);
    }
}

__device__ __forceinline__ void stsA(char* stage, int tid, const float4* aR) {
#pragma unroll
    for (int it = 0; it < 4; ++it) {
        int f = tid + it * 512;
        int m = f >> 4, q = f & 15;
        float4 v = aR[it];
        __half2 h0 = __floats2half2_rn(v.x, v.y);
        __half2 h1 = __floats2half2_rn(v.z, v.w);
        uint32_t off = m * (AROW * 2) + q * 8;
        uint2 H; H.x = *(uint32_t*)&h0; H.y = *(uint32_t*)&h1;
        *(uint2*)(stage + off) = H;
    }
}

// copy B rows [0, nrows) for one K chunk; nrows is 128 (gate-only) or 256
__device__ __forceinline__ void cpB(uint32_t stB, int kbytes, int tid, int nrows) {
    const int iters = nrows >> 6;                // 2 or 4
    for (int it = 0; it < iters; ++it) {
        int f = tid + it * 512;
        int n = f >> 3, q = f & 7;
        uint32_t dst = n * (AROW * 2) + q * 16;
        CP16(stB + dst, (const char*)g_Bh + (size_t)n * (Kt * 2) + kbytes + q * 16);
    }
    CP_COMMIT();
}

__global__ __launch_bounds__(512, 1)
void node_kernel(const float* __restrict__ xinit, const float* __restrict__ xfin,
                 const int* __restrict__ gids,
                 const float* __restrict__ bg, const float* __restrict__ bt) {
    extern __shared__ char smem[];
    __shared__ int s_gid[Mt];
    const uint32_t sbase = smem_u32(smem);
    const int tid = threadIdx.x;
    const int wid = tid >> 5;
    const int l = tid & 31;
    const int wm = wid & 3;          // 0..3 -> 32 rows each
    const int wn = wid >> 2;         // 0..3 -> 64 cols each
    const int nodeBase = blockIdx.x * Mt;

    if (tid < Mt) s_gid[tid] = gids[nodeBase + tid];

    // ldmatrix per-thread offsets (bytes)
    const uint32_t aOff = ((wm * 32 + (l & 15)) * AROW + ((l >> 4) * 8)) * 2;
    const uint32_t bOff = ((wn * 64 + ((l >> 4) & 1) * 8 + (l & 7)) * AROW +
                           ((l >> 3) & 1) * 8) * 2 + OFF_B;

    float acc[2][8][4];
#pragma unroll
    for (int i = 0; i < 2; i++)
#pragma unroll
        for (int j = 0; j < 8; j++)
#pragma unroll
            for (int p = 0; p < 4; p++) acc[i][j][p] = 0.0f;

    float4 rA[2][4];

    // prologue: chunks 0,1 staged; chunk 2 LDG'd into regs; B 0,1 in flight
    ldgA(xinit, nodeBase, 0, tid, rA[0]);
    ldgA(xinit, nodeBase, KC, tid, rA[1]);
    cpB(sbase + OFF_B, 0, tid, 128);                 // group g0
    cpB(sbase + STG + OFF_B, KC * 2, tid, 128);      // group g1
    stsA(smem, tid, rA[0]);
    stsA(smem + STG, tid, rA[1]);
    ldgA(xinit, nodeBase, 2 * KC, tid, rA[0]);       // chunk 2 pending
    CP_WAIT1();                                      // g0 done
    __syncthreads();

    for (int j = 0; j < 8; ++j) {
        const uint32_t stg = sbase + (uint32_t)(j & 3) * STG;
        // B for chunk j+2 (2 ahead)
        if (j + 2 < 8) {
            const int c = j + 2;
            cpB(sbase + (uint32_t)((j + 2) & 3) * STG + OFF_B, c * KC * 2, tid,
                (c < 4) ? 128 : 256);
        }
        // LDG A chunk j+3 (3 ahead)
        if (j + 3 < 8) {
            const int c = j + 3;
            const float* X = (c < 4) ? xinit : xfin;
            ldgA(X, nodeBase, (c & 3) * KC, tid, rA[(j + 1) & 1]);
        }

        // chunks 0-3 hit the init half, where all t-columns of B are zero:
        // t warps (wn >= 2) skip their LDSM+MMA block entirely.
        if (j >= 4 || wn < 2) {
#pragma unroll
            for (int ks = 0; ks < 4; ++ks) {
                const uint32_t aA = stg + aOff + ks * 32;
                uint32_t ah0[4], ah1[4];
                LDSM4(ah0, aA);
                LDSM4(ah1, aA + 16 * AROW * 2);
#pragma unroll
                for (int np = 0; np < 4; ++np) {
                    const uint32_t bA = stg + bOff + np * (16 * AROW * 2) + ks * 32;
                    uint32_t bh[4];
                    LDSM4(bh, bA);
                    MMA(acc[0][2 * np],     ah0, bh[0], bh[1]);
                    MMA(acc[0][2 * np + 1], ah0, bh[2], bh[3]);
                    MMA(acc[1][2 * np],     ah1, bh[0], bh[1]);
                    MMA(acc[1][2 * np + 1], ah1, bh[2], bh[3]);
                }
            }
        }

        // STS chunk j+2 (LDG'd one full iteration ago)
        if (j + 2 < 8) stsA(smem + ((j + 2) & 3) * STG, tid, rA[j & 1]);
        // guarantee B group for chunk j+1 has landed before next iter consumes it
        if (j + 2 < 8)      CP_WAIT1();
        else if (j + 1 < 8) CP_WAIT0();
        __syncthreads();
    }

    // ---- epilogue ----
    float* sOut = (float*)smem;          // [128][OUTROW] fp32, aliases stages
    const int r = l >> 2;
    const int cq = (l & 3) * 2;

    if (wn < 2) {        // gate warps: store raw gate logits
#pragma unroll
        for (int mt = 0; mt < 2; ++mt)
#pragma unroll
            for (int nt = 0; nt < 8; ++nt) {
                int m = wm * 32 + mt * 16 + r;
                int c = wn * 64 + nt * 8 + cq;
                float* p = sOut + m * OUTROW + c;
                p[0] = acc[mt][nt][0];
                p[1] = acc[mt][nt][1];
                p[8 * OUTROW] = acc[mt][nt][2];
                p[8 * OUTROW + 1] = acc[mt][nt][3];
            }
    }
    __syncthreads();
    if (wn >= 2) {       // t warps: out = sigmoid(g + bg) * (t + bt), in place
#pragma unroll
        for (int mt = 0; mt < 2; ++mt)
#pragma unroll
            for (int nt = 0; nt < 8; ++nt) {
                int m = wm * 32 + mt * 16 + r;
                int ct = (wn - 2) * 64 + nt * 8 + cq;
                float bg0 = bg[ct], bg1 = bg[ct + 1];
                float bt0 = bt[ct], bt1 = bt[ct + 1];
                float* p = sOut + m * OUTROW + ct;
                float g0 = p[0], g1 = p[1];
                float g2 = p[8 * OUTROW], g3 = p[8 * OUTROW + 1];
                p[0] = (acc[mt][nt][0] + bt0) / (1.0f + __expf(-(g0 + bg0)));
                p[1] = (acc[mt][nt][1] + bt1) / (1.0f + __expf(-(g1 + bg1)));
                p[8 * OUTROW]     = (acc[mt][nt][2] + bt0) / (1.0f + __expf(-(g2 + bg0)));
                p[8 * OUTROW + 1] = (acc[mt][nt][3] + bt1) / (1.0f + __expf(-(g3 + bg1)));
            }
    }
    __syncthreads();

    // sorted-id run-length segment sum: 4 threads per channel, 32 nodes each
    {
        const int c = tid & 127;
        const int n0 = (tid >> 7) * 32;
        float run = 0.0f;
        int cur = s_gid[n0];
        for (int n = n0; n < n0 + 32; ++n) {
            int g = s_gid[n];
            if (g != cur) {
                atomicAdd(&g_readout[(size_t)cur * Cc + c], run);
                run = 0.0f; cur = g;
            }
            run += sOut[n * OUTROW + c];
        }
        atomicAdd(&g_readout[(size_t)cur * Cc + c], run);
    }
}

// ---------------- kernel: per-column BN stats -> scale/shift ----------------
__global__ __launch_bounds__(256)
void stats_kernel(const float* __restrict__ aux,
                  const float* __restrict__ gamma, const float* __restrict__ beta) {
    const int j = blockIdx.x;
    const int tid = threadIdx.x;
    float s = 0.0f, sq = 0.0f;
    for (int g = tid; g < NGg; g += 256) {
        float v = (j < Cc) ? g_readout[(size_t)g * Cc + j]
                           : aux[(size_t)g * Aa + (j - Cc)];
        s += v; sq += v * v;
    }
#pragma unroll
    for (int o = 16; o; o >>= 1) {
        s  += __shfl_xor_sync(0xffffffffu, s,  o);
        sq += __shfl_xor_sync(0xffffffffu, sq, o);
    }
    __shared__ float ws[8], wq[8];
    if ((tid & 31) == 0) { ws[tid >> 5] = s; wq[tid >> 5] = sq; }
    __syncthreads();
    if (tid == 0) {
        float S = 0.0f, Q = 0.0f;
#pragma unroll
        for (int i = 0; i < 8; i++) { S += ws[i]; Q += wq[i]; }
        float mean = S * (1.0f / NGg);
        float var  = Q * (1.0f / NGg) - mean * mean;
        float sc = gamma[j] * rsqrtf(var + BN_EPS);
        g_scale[j] = sc;
        g_shift[j] = beta[j] - mean * sc;
    }
}

// ---------------- kernel: hidden = relu(norm @ W1 + b1) ----------------
__global__ __launch_bounds__(256)
void mlp1_kernel(const float* __restrict__ aux,
                 const float* __restrict__ W1, const float* __restrict__ b1) {
    __shared__ float sA[64][33];
    __shared__ float sB[32][128];
    const int tid = threadIdx.x;
    const int tm = tid >> 4, tc = tid & 15;
    const int c0 = tc * 8;
    const int rowBase = blockIdx.x * 64;
    const int colBase = blockIdx.y * 128;

    unsigned long long acc[4][4];
#pragma unroll
    for (int i = 0; i < 4; i++)
#pragma unroll
        for (int j = 0; j < 4; j++) acc[i][j] = 0ULL;

    for (int chunk = 0; chunk < 5; ++chunk) {       // K = 160
        const int k0 = chunk * 32;
        __syncthreads();
#pragma unroll
        for (int it = 0; it < 2; ++it) {
            int f = tid + it * 256;
            int n = f >> 3, q = f & 7;
            int j = k0 + 4 * q;
            float4 v;
            if (j < Cc) v = *(const float4*)(g_readout + (size_t)(rowBase + n) * Cc + j);
            else        v = *(const float4*)(aux + (size_t)(rowBase + n) * Aa + (j - Cc));
            float4 sc = *(const float4*)(g_scale + j);
            float4 sh = *(const float4*)(g_shift + j);
            sA[n][4 * q + 0] = fmaf(v.x, sc.x, sh.x);
            sA[n][4 * q + 1] = fmaf(v.y, sc.y, sh.y);
            sA[n][4 * q + 2] = fmaf(v.z, sc.z, sh.z);
            sA[n][4 * q + 3] = fmaf(v.w, sc.w, sh.w);
        }
#pragma unroll
        for (int it = 0; it < 4; ++it) {
            int f = tid + it * 256;
            int k = f >> 5, c4 = (f & 31) * 4;
            *(float4*)&sB[k][c4] = *(const float4*)(W1 + (size_t)(k0 + k) * Gg + colBase + c4);
        }
        __syncthreads();
#pragma unroll 4
        for (int k = 0; k < 32; ++k) {
            unsigned long long av[4];
#pragma unroll
            for (int i = 0; i < 4; i++) { float a = sA[tm * 4 + i][k]; av[i] = pack2(a, a); }
            ulonglong2 wA = *(const ulonglong2*)&sB[k][c0];
            ulonglong2 wB = *(const ulonglong2*)&sB[k][c0 + 4];
#pragma unroll
            for (int i = 0; i < 4; i++) {
                acc[i][0] = fma2(av[i], wA.x, acc[i][0]);
                acc[i][1] = fma2(av[i], wA.y, acc[i][1]);
                acc[i][2] = fma2(av[i], wB.x, acc[i][2]);
                acc[i][3] = fma2(av[i], wB.y, acc[i][3]);
            }
        }
    }
    float bv[8];
#pragma unroll
    for (int j = 0; j < 8; j++) bv[j] = b1[colBase + c0 + j];
#pragma unroll
    for (int i = 0; i < 4; i++) {
        int r = rowBase + tm * 4 + i;
#pragma unroll
        for (int j = 0; j < 4; j++) {
            float lo, hi; unpack2(acc[i][j], lo, hi);
            lo = fmaxf(lo + bv[2 * j], 0.0f);
            hi = fmaxf(hi + bv[2 * j + 1], 0.0f);
            g_hidden[(size_t)r * Gg + colBase + c0 + 2 * j]     = lo;
            g_hidden[(size_t)r * Gg + colBase + c0 + 2 * j + 1] = hi;
        }
    }
}

// ---------------- kernel: logits = hidden @ W2 + b2 ----------------
__global__ __launch_bounds__(256)
void mlp2_kernel(const float* __restrict__ W2, const float* __restrict__ b2,
                 float* __restrict__ out) {
    __shared__ float sA[16][65];
    __shared__ float sB[64][128];
    const int tid = threadIdx.x;
    const int tm = tid >> 4, tc = tid & 15;
    const int c0 = tc * 8;
    const int rowBase = blockIdx.x * 16;

    unsigned long long acc[4] = {0ULL, 0ULL, 0ULL, 0ULL};
    for (int chunk = 0; chunk < 8; ++chunk) {       // K = 512
        const int k0 = chunk * 64;
        __syncthreads();
        {
            int n = tid >> 4, q = tid & 15;
            float4 v = *(const float4*)(g_hidden + (size_t)(rowBase + n) * Gg + k0 + 4 * q);
            sA[n][4 * q + 0] = v.x; sA[n][4 * q + 1] = v.y;
            sA[n][4 * q + 2] = v.z; sA[n][4 * q + 3] = v.w;
        }
#pragma unroll
        for (int it = 0; it < 8; ++it) {
            int f = tid + it * 256;
            int k = f >> 5, c4 = (f & 31) * 4;
            *(float4*)&sB[k][c4] = *(const float4*)(W2 + (size_t)(k0 + k) * Cc + c4);
        }
        __syncthreads();
#pragma unroll 8
        for (int k = 0; k < 64; ++k) {
            float a = sA[tm][k];
            unsigned long long av = pack2(a, a);
            ulonglong2 wA = *(const ulonglong2*)&sB[k][c0];
            ulonglong2 wB = *(const ulonglong2*)&sB[k][c0 + 4];
            acc[0] = fma2(av, wA.x, acc[0]);
            acc[1] = fma2(av, wA.y, acc[1]);
            acc[2] = fma2(av, wB.x, acc[2]);
            acc[3] = fma2(av, wB.y, acc[3]);
        }
    }
#pragma unroll
    for (int j = 0; j < 4; j++) {
        float lo, hi; unpack2(acc[j], lo, hi);
        int r = rowBase + tm;
        out[(size_t)r * Cc + c0 + 2 * j]     = lo + b2[c0 + 2 * j];
        out[(size_t)r * Cc + c0 + 2 * j + 1] = hi + b2[c0 + 2 * j + 1];
    }
}

// ---------------- launch ----------------
extern "C" void kernel_launch(void* const* d_in, const int* in_sizes, int n_in,
                              void* d_out, int out_size) {
    (void)in_sizes; (void)out_size;
    const float* xinit = (const float*)d_in[0];
    const float* xfin  = (const float*)d_in[1];
    const float* aux   = (const float*)d_in[2];
    const int*   gid   = (const int*)d_in[3];
    const int wb = (n_in >= 15) ? 5 : 4;
    const float* Wg    = (const float*)d_in[wb + 0];
    const float* bg    = (const float*)d_in[wb + 1];
    const float* Wt    = (const float*)d_in[wb + 2];
    const float* bt    = (const float*)d_in[wb + 3];
    const float* gamma = (const float*)d_in[wb + 4];
    const float* beta  = (const float*)d_in[wb + 5];
    const float* W1    = (const float*)d_in[wb + 6];
    const float* b1    = (const float*)d_in[wb + 7];
    const float* W2    = (const float*)d_in[wb + 8];
    const float* b2    = (const float*)d_in[wb + 9];

    cudaFuncSetAttribute(node_kernel, cudaFuncAttributeMaxDynamicSharedMemorySize, SMEM_DYN);

    prep_kernel<<<(Nt * Kt) / 256, 256>>>(Wg, Wt);   // also zeroes g_readout
    node_kernel<<<Nn / Mt, 512, SMEM_DYN>>>(xinit, xfin, gid, bg, bt);
    stats_kernel<<<CpA, 256>>>(aux, gamma, beta);
    mlp1_kernel<<<dim3(NGg / 64, Gg / 128), 256>>>(aux, W1, b1);
    mlp2_kernel<<<NGg / 16, 256>>>(W2, b2, (float*)d_out);
}